// round 1
// baseline (speedup 1.0000x reference)
#include <cuda_runtime.h>
#include <math.h>

#define BATCH 8
#define CDIM  256
#define NDIM  4096
#define CQKD  32
#define ATT_SCALE 0.1767766952966369f   // 1/sqrt(32)

// ---------------- scratch (device globals: sanctioned workaround) -------------
__device__ float g_q[(size_t)BATCH * NDIM * CQKD];      // [B,N,32]
__device__ float g_k[(size_t)BATCH * NDIM * CQKD];      // [B,N,32]
__device__ float g_v[(size_t)BATCH * CDIM * NDIM];      // [B,C,N]
__device__ float g_attn_fb[(size_t)BATCH * NDIM * NDIM];// fallback if attn not in d_out
__device__ float g_tex_fb[(size_t)BATCH * CDIM * NDIM]; // fallback if texture not in d_out

// ---------------- q / k projection: Y[b,n,o] = sum_c W[o,c] X[b,c,n] + b[o] ---
__global__ void proj_small_kernel(const float* __restrict__ X,
                                  const float* __restrict__ W,
                                  const float* __restrict__ bias,
                                  float* __restrict__ Y)
{
    __shared__ float Ws[CQKD * CDIM];   // 32KB
    int tid = threadIdx.x;
    for (int i = tid; i < CQKD * CDIM; i += 256) Ws[i] = W[i];
    __syncthreads();

    int b = blockIdx.y;
    int n = blockIdx.x * 256 + tid;
    const float* Xp = X + (size_t)b * CDIM * NDIM + n;

    float acc[CQKD];
#pragma unroll
    for (int o = 0; o < CQKD; o++) acc[o] = bias[o];

    for (int c = 0; c < CDIM; c++) {
        float x = Xp[(size_t)c * NDIM];
#pragma unroll
        for (int o = 0; o < CQKD; o++) acc[o] += x * Ws[o * CDIM + c];
    }
    float* Yp = Y + ((size_t)b * NDIM + n) * CQKD;
#pragma unroll
    for (int o = 0; o < CQKD; o++) Yp[o] = acc[o];
}

// ---------------- v projection: V[b,c,n] = sum_c' Wv[c,c'] X[b,c',n] + bv[c] --
__global__ void proj_v_kernel(const float* __restrict__ X,
                              const float* __restrict__ Wv,
                              const float* __restrict__ bv,
                              float* __restrict__ V)
{
    __shared__ float Ws[32 * CDIM];     // 32 output-channel rows, 32KB
    int tid = threadIdx.x;
    int c0 = blockIdx.y * 32;
    for (int i = tid; i < 32 * CDIM; i += 256) Ws[i] = Wv[(size_t)c0 * CDIM + i];
    __syncthreads();

    int b = blockIdx.z;
    int n = blockIdx.x * 256 + tid;
    const float* Xp = X + (size_t)b * CDIM * NDIM + n;

    float acc[32];
#pragma unroll
    for (int i = 0; i < 32; i++) acc[i] = bv[c0 + i];

    for (int c = 0; c < CDIM; c++) {
        float x = Xp[(size_t)c * NDIM];
#pragma unroll
        for (int i = 0; i < 32; i++) acc[i] += x * Ws[i * CDIM + c];
    }
    float* Vp = V + ((size_t)b * CDIM + c0) * NDIM + n;
#pragma unroll
    for (int i = 0; i < 32; i++) Vp[(size_t)i * NDIM] = acc[i];
}

// ---------------- energy: E[b,m,n] = SCALE * dot(q[b,m,:], k[b,n,:]) ----------
__global__ void energy_kernel(const float* __restrict__ Q,
                              const float* __restrict__ K,
                              float* __restrict__ E)
{
    __shared__ float qs[CQKD][64 + 4];  // transposed: qs[k][m]
    __shared__ float ks[CQKD][64 + 4];  // transposed: ks[k][n]

    int tid = threadIdx.x;
    int b  = blockIdx.z;
    int m0 = blockIdx.y * 64;
    int n0 = blockIdx.x * 64;

    const float* Qb = Q + ((size_t)b * NDIM + m0) * CQKD;
    const float* Kb = K + ((size_t)b * NDIM + n0) * CQKD;

    int r  = tid >> 3;          // 0..31
    int c4 = (tid & 7) * 4;     // 0..28
#pragma unroll
    for (int g = 0; g < 2; g++) {
        int rr = r + g * 32;
        float4 qv = *(const float4*)(Qb + (size_t)rr * CQKD + c4);
        qs[c4 + 0][rr] = qv.x; qs[c4 + 1][rr] = qv.y;
        qs[c4 + 2][rr] = qv.z; qs[c4 + 3][rr] = qv.w;
        float4 kv = *(const float4*)(Kb + (size_t)rr * CQKD + c4);
        ks[c4 + 0][rr] = kv.x; ks[c4 + 1][rr] = kv.y;
        ks[c4 + 2][rr] = kv.z; ks[c4 + 3][rr] = kv.w;
    }
    __syncthreads();

    int tx = tid & 15, ty = tid >> 4;
    float acc[4][4] = {};
#pragma unroll
    for (int k = 0; k < CQKD; k++) {
        float a[4], bb[4];
#pragma unroll
        for (int i = 0; i < 4; i++) { a[i] = qs[k][ty * 4 + i]; bb[i] = ks[k][tx * 4 + i]; }
#pragma unroll
        for (int i = 0; i < 4; i++)
#pragma unroll
            for (int j = 0; j < 4; j++) acc[i][j] += a[i] * bb[j];
    }

    float* Eb = E + ((size_t)b * NDIM + m0) * NDIM + n0;
#pragma unroll
    for (int i = 0; i < 4; i++) {
        float4 v;
        v.x = acc[i][0] * ATT_SCALE; v.y = acc[i][1] * ATT_SCALE;
        v.z = acc[i][2] * ATT_SCALE; v.w = acc[i][3] * ATT_SCALE;
        *(float4*)(Eb + (size_t)(ty * 4 + i) * NDIM + tx * 4) = v;
    }
}

// ---------------- softmax over each row of 4096, in place ---------------------
__global__ void softmax_kernel(float* __restrict__ A)
{
    __shared__ float smax[8];
    __shared__ float ssum[8];
    size_t base = (size_t)blockIdx.x * NDIM;
    int tid = threadIdx.x;       // 256 threads, 16 floats each

    float4 v[4];
    float mx = -3.4e38f;
#pragma unroll
    for (int g = 0; g < 4; g++) {
        v[g] = *(const float4*)(A + base + (size_t)(g * 256 + tid) * 4);
        mx = fmaxf(mx, fmaxf(fmaxf(v[g].x, v[g].y), fmaxf(v[g].z, v[g].w)));
    }
#pragma unroll
    for (int o = 16; o > 0; o >>= 1) mx = fmaxf(mx, __shfl_xor_sync(0xffffffffu, mx, o));
    if ((tid & 31) == 0) smax[tid >> 5] = mx;
    __syncthreads();
    mx = smax[0];
#pragma unroll
    for (int w = 1; w < 8; w++) mx = fmaxf(mx, smax[w]);

    float s = 0.f;
#pragma unroll
    for (int g = 0; g < 4; g++) {
        v[g].x = __expf(v[g].x - mx); v[g].y = __expf(v[g].y - mx);
        v[g].z = __expf(v[g].z - mx); v[g].w = __expf(v[g].w - mx);
        s += v[g].x + v[g].y + v[g].z + v[g].w;
    }
#pragma unroll
    for (int o = 16; o > 0; o >>= 1) s += __shfl_xor_sync(0xffffffffu, s, o);
    if ((tid & 31) == 0) ssum[tid >> 5] = s;
    __syncthreads();
    s = 0.f;
#pragma unroll
    for (int w = 0; w < 8; w++) s += ssum[w];

    float inv = 1.0f / s;
#pragma unroll
    for (int g = 0; g < 4; g++) {
        v[g].x *= inv; v[g].y *= inv; v[g].z *= inv; v[g].w *= inv;
        *(float4*)(A + base + (size_t)(g * 256 + tid) * 4) = v[g];
    }
}

// ---------------- texture GEMM + epilogue -------------------------------------
// tex[b,c,m] = sum_n v[b,c,n] * attn[b,m,n];  out = tex + sketches
// Tiles: 64 (c) x 128 (m) x 32 (n), 256 threads, 4x8 per thread.
__global__ void texture_kernel(const float* __restrict__ V,
                               const float* __restrict__ A,
                               const float* __restrict__ SK,
                               float* __restrict__ TEX,
                               float* __restrict__ OUT)
{
    __shared__ float As[32][64 + 4];    // As[k][i] (v transposed)
    __shared__ float Bs[32][128 + 4];   // Bs[k][j] (attn transposed)

    int tid = threadIdx.x;
    int b  = blockIdx.z;
    int i0 = blockIdx.y * 64;    // c
    int j0 = blockIdx.x * 128;   // m

    const float* Vb = V + ((size_t)b * CDIM + i0) * NDIM;
    const float* Ab = A + ((size_t)b * NDIM + j0) * NDIM;

    int r  = tid >> 3;           // 0..31
    int c4 = (tid & 7) * 4;      // 0..28
    int tx = tid & 15, ty = tid >> 4;

    float acc[4][8];
#pragma unroll
    for (int i = 0; i < 4; i++)
#pragma unroll
        for (int j = 0; j < 8; j++) acc[i][j] = 0.f;

    for (int kt = 0; kt < NDIM; kt += 32) {
#pragma unroll
        for (int g = 0; g < 2; g++) {
            int rr = r + g * 32;
            float4 x = *(const float4*)(Vb + (size_t)rr * NDIM + kt + c4);
            As[c4 + 0][rr] = x.x; As[c4 + 1][rr] = x.y;
            As[c4 + 2][rr] = x.z; As[c4 + 3][rr] = x.w;
        }
#pragma unroll
        for (int g = 0; g < 4; g++) {
            int rr = r + g * 32;
            float4 x = *(const float4*)(Ab + (size_t)rr * NDIM + kt + c4);
            Bs[c4 + 0][rr] = x.x; Bs[c4 + 1][rr] = x.y;
            Bs[c4 + 2][rr] = x.z; Bs[c4 + 3][rr] = x.w;
        }
        __syncthreads();

#pragma unroll
        for (int k = 0; k < 32; k++) {
            float4 a4 = *(const float4*)&As[k][ty * 4];
            float4 b0 = *(const float4*)&Bs[k][tx * 8];
            float4 b1 = *(const float4*)&Bs[k][tx * 8 + 4];
            float av[4] = {a4.x, a4.y, a4.z, a4.w};
            float bv[8] = {b0.x, b0.y, b0.z, b0.w, b1.x, b1.y, b1.z, b1.w};
#pragma unroll
            for (int i = 0; i < 4; i++)
#pragma unroll
                for (int j = 0; j < 8; j++) acc[i][j] += av[i] * bv[j];
        }
        __syncthreads();
    }

#pragma unroll
    for (int ii = 0; ii < 4; ii++) {
        int i = i0 + ty * 4 + ii;
        size_t off = ((size_t)b * CDIM + i) * NDIM + j0 + tx * 8;
        float4 t0 = {acc[ii][0], acc[ii][1], acc[ii][2], acc[ii][3]};
        float4 t1 = {acc[ii][4], acc[ii][5], acc[ii][6], acc[ii][7]};
        *(float4*)(TEX + off)     = t0;
        *(float4*)(TEX + off + 4) = t1;
        float4 s0 = *(const float4*)(SK + off);
        float4 s1 = *(const float4*)(SK + off + 4);
        float4 o0 = {t0.x + s0.x, t0.y + s0.y, t0.z + s0.z, t0.w + s0.w};
        float4 o1 = {t1.x + s1.x, t1.y + s1.y, t1.z + s1.z, t1.w + s1.w};
        *(float4*)(OUT + off)     = o0;
        *(float4*)(OUT + off + 4) = o1;
    }
}

// ---------------- launch -------------------------------------------------------
extern "C" void kernel_launch(void* const* d_in, const int* in_sizes, int n_in,
                              void* d_out, int out_size)
{
    const float* sk = (const float*)d_in[0];
    const float* ex = (const float*)d_in[1];
    const float* Wq = (const float*)d_in[2];
    const float* bq = (const float*)d_in[3];
    const float* Wk = (const float*)d_in[4];
    const float* bk = (const float*)d_in[5];
    const float* Wv = (const float*)d_in[6];
    const float* bv = (const float*)d_in[7];

    const size_t BCN = (size_t)BATCH * CDIM * NDIM;          // 8,388,608
    const size_t BNN = (size_t)BATCH * NDIM * NDIM;          // 134,217,728

    float* out_p = (float*)d_out;
    float* tex_p;
    float* attn_p;

    if ((size_t)(unsigned)out_size >= 2 * BCN + BNN) {
        tex_p  = out_p + BCN;
        attn_p = out_p + 2 * BCN;
    } else {
        // fallback: only `out` fits in d_out; keep the rest in scratch
        void* p;
        cudaGetSymbolAddress(&p, g_tex_fb);  tex_p  = (float*)p;
        cudaGetSymbolAddress(&p, g_attn_fb); attn_p = (float*)p;
    }

    float* q_p; float* k_p; float* v_p;
    { void* p;
      cudaGetSymbolAddress(&p, g_q); q_p = (float*)p;
      cudaGetSymbolAddress(&p, g_k); k_p = (float*)p;
      cudaGetSymbolAddress(&p, g_v); v_p = (float*)p; }

    // 1) q, k projections
    dim3 gproj(NDIM / 256, BATCH);
    proj_small_kernel<<<gproj, 256>>>(sk, Wq, bq, q_p);
    proj_small_kernel<<<gproj, 256>>>(ex, Wk, bk, k_p);

    // 2) v projection
    dim3 gv(NDIM / 256, CDIM / 32, BATCH);
    proj_v_kernel<<<gv, 256>>>(ex, Wv, bv, v_p);

    // 3) energy -> raw scores into attention buffer
    dim3 ge(NDIM / 64, NDIM / 64, BATCH);
    energy_kernel<<<ge, 256>>>(q_p, k_p, attn_p);

    // 4) softmax in place
    softmax_kernel<<<BATCH * NDIM, 256>>>(attn_p);

    // 5) texture GEMM + residual epilogue
    dim3 gt(NDIM / 128, CDIM / 64, BATCH);
    texture_kernel<<<gt, 256>>>(v_p, attn_p, sk, tex_p, out_p);
}

// round 4
// speedup vs baseline: 1.4991x; 1.4991x over previous
#include <cuda_runtime.h>
#include <math.h>
#include <stdint.h>

#define BATCH 8
#define CDIM  256
#define NDIM  4096
#define CQKD  32
#define ATT_SCALE 0.1767766952966369f   // 1/sqrt(32)

// ---------------- scratch (device globals: sanctioned workaround) -------------
__device__ float g_q[(size_t)BATCH * NDIM * CQKD];      // [B,N,32]
__device__ float g_k[(size_t)BATCH * NDIM * CQKD];      // [B,N,32]
__device__ float g_v[(size_t)BATCH * CDIM * NDIM];      // [B,C,N]
__device__ float g_attn_fb[(size_t)BATCH * NDIM * NDIM];// fallback if attn not in d_out
__device__ float g_tex_fb[(size_t)BATCH * CDIM * NDIM]; // fallback if texture not in d_out

// =============================== PTX helpers ==================================
__device__ __forceinline__ uint32_t smem_u32(const void* p) {
    uint32_t a;
    asm("{ .reg .u64 t; cvta.to.shared.u64 t, %1; cvt.u32.u64 %0, t; }"
        : "=r"(a) : "l"(p));
    return a;
}
__device__ __forceinline__ void cp16(uint32_t dst, const void* src) {
    asm volatile("cp.async.cg.shared.global [%0], [%1], 16;" :: "r"(dst), "l"(src) : "memory");
}
#define CP_COMMIT() asm volatile("cp.async.commit_group;" ::: "memory")
#define CP_WAIT2()  asm volatile("cp.async.wait_group 2;"  ::: "memory")
#define CP_WAIT0()  asm volatile("cp.async.wait_group 0;"  ::: "memory")

// 3xTF32 split: tensor core reads only the top 19 bits of each fp32 register.
__device__ __forceinline__ uint32_t tf_hi(float x) {
    return __float_as_uint(x) & 0xFFFFE000u;
}
__device__ __forceinline__ uint32_t tf_lo(float x, uint32_t hi) {
    return __float_as_uint(x - __uint_as_float(hi));
}
__device__ __forceinline__ void mma_tf32(float* c, const uint32_t* a, const uint32_t* b) {
    asm volatile(
        "mma.sync.aligned.m16n8k8.row.col.f32.tf32.tf32.f32 "
        "{%0,%1,%2,%3}, {%4,%5,%6,%7}, {%8,%9}, {%0,%1,%2,%3};"
        : "+f"(c[0]), "+f"(c[1]), "+f"(c[2]), "+f"(c[3])
        : "r"(a[0]), "r"(a[1]), "r"(a[2]), "r"(a[3]), "r"(b[0]), "r"(b[1]));
}

// ---------------- q / k projection: Y[b,n,o] = sum_c W[o,c] X[b,c,n] + b[o] ---
__global__ void proj_small_kernel(const float* __restrict__ X,
                                  const float* __restrict__ W,
                                  const float* __restrict__ bias,
                                  float* __restrict__ Y)
{
    __shared__ float Ws[CQKD * CDIM];   // 32KB
    int tid = threadIdx.x;
    for (int i = tid; i < CQKD * CDIM; i += 256) Ws[i] = W[i];
    __syncthreads();

    int b = blockIdx.y;
    int n = blockIdx.x * 256 + tid;
    const float* Xp = X + (size_t)b * CDIM * NDIM + n;

    float acc[CQKD];
#pragma unroll
    for (int o = 0; o < CQKD; o++) acc[o] = bias[o];

    for (int c = 0; c < CDIM; c++) {
        float x = Xp[(size_t)c * NDIM];
#pragma unroll
        for (int o = 0; o < CQKD; o++) acc[o] += x * Ws[o * CDIM + c];
    }
    float* Yp = Y + ((size_t)b * NDIM + n) * CQKD;
#pragma unroll
    for (int o = 0; o < CQKD; o++) Yp[o] = acc[o];
}

// ---------------- v projection: V[b,c,n] = sum_c' Wv[c,c'] X[b,c',n] + bv[c] --
__global__ void proj_v_kernel(const float* __restrict__ X,
                              const float* __restrict__ Wv,
                              const float* __restrict__ bv,
                              float* __restrict__ V)
{
    __shared__ float Ws[32 * CDIM];     // 32KB
    int tid = threadIdx.x;
    int c0 = blockIdx.y * 32;
    for (int i = tid; i < 32 * CDIM; i += 256) Ws[i] = Wv[(size_t)c0 * CDIM + i];
    __syncthreads();

    int b = blockIdx.z;
    int n = blockIdx.x * 256 + tid;
    const float* Xp = X + (size_t)b * CDIM * NDIM + n;

    float acc[32];
#pragma unroll
    for (int i = 0; i < 32; i++) acc[i] = bv[c0 + i];

    for (int c = 0; c < CDIM; c++) {
        float x = Xp[(size_t)c * NDIM];
#pragma unroll
        for (int i = 0; i < 32; i++) acc[i] += x * Ws[i * CDIM + c];
    }
    float* Vp = V + ((size_t)b * CDIM + c0) * NDIM + n;
#pragma unroll
    for (int i = 0; i < 32; i++) Vp[(size_t)i * NDIM] = acc[i];
}

// ---------------- energy: E[b,m,n] = SCALE * dot(q[b,m,:], k[b,n,:]) ----------
__global__ void energy_kernel(const float* __restrict__ Q,
                              const float* __restrict__ K,
                              float* __restrict__ E)
{
    __shared__ float qs[CQKD][64 + 4];
    __shared__ float ks[CQKD][64 + 4];

    int tid = threadIdx.x;
    int b  = blockIdx.z;
    int m0 = blockIdx.y * 64;
    int n0 = blockIdx.x * 64;

    const float* Qb = Q + ((size_t)b * NDIM + m0) * CQKD;
    const float* Kb = K + ((size_t)b * NDIM + n0) * CQKD;

    int r  = tid >> 3;
    int c4 = (tid & 7) * 4;
#pragma unroll
    for (int g = 0; g < 2; g++) {
        int rr = r + g * 32;
        float4 qv = *(const float4*)(Qb + (size_t)rr * CQKD + c4);
        qs[c4 + 0][rr] = qv.x; qs[c4 + 1][rr] = qv.y;
        qs[c4 + 2][rr] = qv.z; qs[c4 + 3][rr] = qv.w;
        float4 kv = *(const float4*)(Kb + (size_t)rr * CQKD + c4);
        ks[c4 + 0][rr] = kv.x; ks[c4 + 1][rr] = kv.y;
        ks[c4 + 2][rr] = kv.z; ks[c4 + 3][rr] = kv.w;
    }
    __syncthreads();

    int tx = tid & 15, ty = tid >> 4;
    float acc[4][4] = {};
#pragma unroll
    for (int k = 0; k < CQKD; k++) {
        float a[4], bb[4];
#pragma unroll
        for (int i = 0; i < 4; i++) { a[i] = qs[k][ty * 4 + i]; bb[i] = ks[k][tx * 4 + i]; }
#pragma unroll
        for (int i = 0; i < 4; i++)
#pragma unroll
            for (int j = 0; j < 4; j++) acc[i][j] += a[i] * bb[j];
    }

    float* Eb = E + ((size_t)b * NDIM + m0) * NDIM + n0;
#pragma unroll
    for (int i = 0; i < 4; i++) {
        float4 v;
        v.x = acc[i][0] * ATT_SCALE; v.y = acc[i][1] * ATT_SCALE;
        v.z = acc[i][2] * ATT_SCALE; v.w = acc[i][3] * ATT_SCALE;
        *(float4*)(Eb + (size_t)(ty * 4 + i) * NDIM + tx * 4) = v;
    }
}

// ---------------- softmax over each row of 4096, in place ---------------------
__global__ void softmax_kernel(float* __restrict__ A)
{
    __shared__ float smax[8];
    __shared__ float ssum[8];
    size_t base = (size_t)blockIdx.x * NDIM;
    int tid = threadIdx.x;

    float4 v[4];
    float mx = -3.4e38f;
#pragma unroll
    for (int g = 0; g < 4; g++) {
        v[g] = *(const float4*)(A + base + (size_t)(g * 256 + tid) * 4);
        mx = fmaxf(mx, fmaxf(fmaxf(v[g].x, v[g].y), fmaxf(v[g].z, v[g].w)));
    }
#pragma unroll
    for (int o = 16; o > 0; o >>= 1) mx = fmaxf(mx, __shfl_xor_sync(0xffffffffu, mx, o));
    if ((tid & 31) == 0) smax[tid >> 5] = mx;
    __syncthreads();
    mx = smax[0];
#pragma unroll
    for (int w = 1; w < 8; w++) mx = fmaxf(mx, smax[w]);

    float s = 0.f;
#pragma unroll
    for (int g = 0; g < 4; g++) {
        v[g].x = __expf(v[g].x - mx); v[g].y = __expf(v[g].y - mx);
        v[g].z = __expf(v[g].z - mx); v[g].w = __expf(v[g].w - mx);
        s += v[g].x + v[g].y + v[g].z + v[g].w;
    }
#pragma unroll
    for (int o = 16; o > 0; o >>= 1) s += __shfl_xor_sync(0xffffffffu, s, o);
    if ((tid & 31) == 0) ssum[tid >> 5] = s;
    __syncthreads();
    s = 0.f;
#pragma unroll
    for (int w = 0; w < 8; w++) s += ssum[w];

    float inv = 1.0f / s;
#pragma unroll
    for (int g = 0; g < 4; g++) {
        v[g].x *= inv; v[g].y *= inv; v[g].z *= inv; v[g].w *= inv;
        *(float4*)(A + base + (size_t)(g * 256 + tid) * 4) = v[g];
    }
}

// ============== texture GEMM via mma.sync 3xTF32 (fp32 accuracy) ==============
// tex[b,c,m] = sum_n V[b,c,n] * attn[b,m,n];  out = tex + sketches
// CTA tile 128(c) x 128(m), K chunks of 32; 8 warps of 64x32; 4-stage cp.async.
#define XM 128
#define XN 128
#define XK 32
#define XLD 36                         // 32 + 4 pad (floats)
#define XSTAGE_FLOATS ((XM + XN) * XLD)   // 9216
#define XSTAGES 4
#define XSMEM_BYTES (XSTAGES * XSTAGE_FLOATS * 4)   // 147456
#define XNCH (NDIM / XK)               // 128

__device__ __forceinline__ void x_load_chunk(int j, uint32_t smem_base,
                                             const float* Vb, const float* Ab, int tid)
{
    uint32_t sb = smem_base + (uint32_t)(j & (XSTAGES - 1)) * (XSTAGE_FLOATS * 4);
    int row  = tid >> 1;               // 0..127
    int half = tid & 1;                // 0..1
    int kt = j * XK;
    int colf = half * 16;              // float col offset

    const float* srcA = Vb + (size_t)row * NDIM + kt + colf;
    uint32_t dstA = sb + ((uint32_t)row * XLD + colf) * 4;
#pragma unroll
    for (int q = 0; q < 4; q++) cp16(dstA + q * 16, srcA + q * 4);

    const float* srcB = Ab + (size_t)row * NDIM + kt + colf;
    uint32_t dstB = sb + (uint32_t)(XM * XLD) * 4 + ((uint32_t)row * XLD + colf) * 4;
#pragma unroll
    for (int q = 0; q < 4; q++) cp16(dstB + q * 16, srcB + q * 4);
}

__global__ void __launch_bounds__(256, 1)
texture_mma_kernel(const float* __restrict__ V,
                   const float* __restrict__ A,
                   const float* __restrict__ SK,
                   float* __restrict__ TEX,
                   float* __restrict__ OUT)
{
    extern __shared__ float smem[];
    uint32_t smem_base = smem_u32(smem);
    int tid = threadIdx.x;
    int wid = tid >> 5;
    int lid = tid & 31;
    int g = lid >> 2;                  // 0..7
    int t = lid & 3;                   // 0..3
    int wm = wid & 1;                  // 0..1 -> 64 c-rows
    int wn = wid >> 1;                 // 0..3 -> 32 m-cols

    int b  = blockIdx.z;
    int i0 = blockIdx.y * XM;          // c offset
    int j0 = blockIdx.x * XN;          // m offset

    const float* Vb = V + ((size_t)b * CDIM + i0) * NDIM;
    const float* Ab = A + ((size_t)b * NDIM + j0) * NDIM;

    float acc[4][4][4];
#pragma unroll
    for (int mt = 0; mt < 4; mt++)
#pragma unroll
        for (int nt = 0; nt < 4; nt++)
#pragma unroll
            for (int q = 0; q < 4; q++) acc[mt][nt][q] = 0.f;

    // prologue: stages 0..2
    x_load_chunk(0, smem_base, Vb, Ab, tid); CP_COMMIT();
    x_load_chunk(1, smem_base, Vb, Ab, tid); CP_COMMIT();
    x_load_chunk(2, smem_base, Vb, Ab, tid); CP_COMMIT();

    for (int i = 0; i < XNCH; i++) {
        CP_WAIT2();
        __syncthreads();
        if (i + 3 < XNCH) x_load_chunk(i + 3, smem_base, Vb, Ab, tid);
        CP_COMMIT();

        const float* sA = smem + (size_t)(i & (XSTAGES - 1)) * XSTAGE_FLOATS;
        const float* sB = sA + XM * XLD;

#pragma unroll
        for (int k0 = 0; k0 < XK; k0 += 8) {
            // A fragments (m16n8k8 row-major):
            // a0=(r,t) a1=(r+8,t) a2=(r,t+4) a3=(r+8,t+4)
            uint32_t ah[4][4], al[4][4];
#pragma unroll
            for (int mt = 0; mt < 4; mt++) {
                int r0 = wm * 64 + mt * 16 + g;
                float x0 = sA[r0 * XLD + k0 + t];
                float x1 = sA[(r0 + 8) * XLD + k0 + t];
                float x2 = sA[r0 * XLD + k0 + t + 4];
                float x3 = sA[(r0 + 8) * XLD + k0 + t + 4];
                ah[mt][0] = tf_hi(x0); al[mt][0] = tf_lo(x0, ah[mt][0]);
                ah[mt][1] = tf_hi(x1); al[mt][1] = tf_lo(x1, ah[mt][1]);
                ah[mt][2] = tf_hi(x2); al[mt][2] = tf_lo(x2, ah[mt][2]);
                ah[mt][3] = tf_hi(x3); al[mt][3] = tf_lo(x3, ah[mt][3]);
            }
            // B fragments: b0=(k=t, n=g) b1=(k=t+4, n=g)
            uint32_t bh[4][2], bl[4][2];
#pragma unroll
            for (int nt = 0; nt < 4; nt++) {
                int n0 = wn * 32 + nt * 8 + g;
                float y0 = sB[n0 * XLD + k0 + t];
                float y1 = sB[n0 * XLD + k0 + t + 4];
                bh[nt][0] = tf_hi(y0); bl[nt][0] = tf_lo(y0, bh[nt][0]);
                bh[nt][1] = tf_hi(y1); bl[nt][1] = tf_lo(y1, bh[nt][1]);
            }
#pragma unroll
            for (int mt = 0; mt < 4; mt++)
#pragma unroll
                for (int nt = 0; nt < 4; nt++) {
                    mma_tf32(acc[mt][nt], ah[mt], bh[nt]);
                    mma_tf32(acc[mt][nt], al[mt], bh[nt]);
                    mma_tf32(acc[mt][nt], ah[mt], bl[nt]);
                }
        }
        __syncthreads();
    }
    CP_WAIT0();

    // epilogue: write tex and out = tex + sketches
#pragma unroll
    for (int mt = 0; mt < 4; mt++) {
        int r0 = i0 + wm * 64 + mt * 16 + g;
#pragma unroll
        for (int nt = 0; nt < 4; nt++) {
            int col = j0 + wn * 32 + nt * 8 + 2 * t;
            size_t off0 = ((size_t)b * CDIM + r0) * NDIM + col;
            size_t off1 = ((size_t)b * CDIM + r0 + 8) * NDIM + col;

            float2 t0 = {acc[mt][nt][0], acc[mt][nt][1]};
            float2 t1 = {acc[mt][nt][2], acc[mt][nt][3]};
            float2 s0 = *(const float2*)(SK + off0);
            float2 s1 = *(const float2*)(SK + off1);
            *(float2*)(TEX + off0) = t0;
            *(float2*)(TEX + off1) = t1;
            float2 o0 = {t0.x + s0.x, t0.y + s0.y};
            float2 o1 = {t1.x + s1.x, t1.y + s1.y};
            *(float2*)(OUT + off0) = o0;
            *(float2*)(OUT + off1) = o1;
        }
    }
}

// ---------------- launch -------------------------------------------------------
extern "C" void kernel_launch(void* const* d_in, const int* in_sizes, int n_in,
                              void* d_out, int out_size)
{
    const float* sk = (const float*)d_in[0];
    const float* ex = (const float*)d_in[1];
    const float* Wq = (const float*)d_in[2];
    const float* bq = (const float*)d_in[3];
    const float* Wk = (const float*)d_in[4];
    const float* bk = (const float*)d_in[5];
    const float* Wv = (const float*)d_in[6];
    const float* bv = (const float*)d_in[7];

    const size_t BCN = (size_t)BATCH * CDIM * NDIM;          // 8,388,608
    const size_t BNN = (size_t)BATCH * NDIM * NDIM;          // 134,217,728

    float* out_p = (float*)d_out;
    float* tex_p;
    float* attn_p;

    if ((size_t)(unsigned)out_size >= 2 * BCN + BNN) {
        tex_p  = out_p + BCN;
        attn_p = out_p + 2 * BCN;
    } else {
        void* p;
        cudaGetSymbolAddress(&p, g_tex_fb);  tex_p  = (float*)p;
        cudaGetSymbolAddress(&p, g_attn_fb); attn_p = (float*)p;
    }

    float* q_p; float* k_p; float* v_p;
    { void* p;
      cudaGetSymbolAddress(&p, g_q); q_p = (float*)p;
      cudaGetSymbolAddress(&p, g_k); k_p = (float*)p;
      cudaGetSymbolAddress(&p, g_v); v_p = (float*)p; }

    // 1) q, k projections
    dim3 gproj(NDIM / 256, BATCH);
    proj_small_kernel<<<gproj, 256>>>(sk, Wq, bq, q_p);
    proj_small_kernel<<<gproj, 256>>>(ex, Wk, bk, k_p);

    // 2) v projection
    dim3 gv(NDIM / 256, CDIM / 32, BATCH);
    proj_v_kernel<<<gv, 256>>>(ex, Wv, bv, v_p);

    // 3) energy -> raw scores into attention buffer
    dim3 ge(NDIM / 64, NDIM / 64, BATCH);
    energy_kernel<<<ge, 256>>>(q_p, k_p, attn_p);

    // 4) softmax in place
    softmax_kernel<<<BATCH * NDIM, 256>>>(attn_p);

    // 5) texture GEMM on tensor cores (3xTF32 mma.sync) + residual epilogue
    static int smem_set = 0;
    if (!smem_set) {
        cudaFuncSetAttribute(texture_mma_kernel,
                             cudaFuncAttributeMaxDynamicSharedMemorySize, XSMEM_BYTES);
        smem_set = 1;
    }
    dim3 gt(NDIM / XN, CDIM / XM, BATCH);
    texture_mma_kernel<<<gt, 256, XSMEM_BYTES>>>(v_p, attn_p, sk, tex_p, out_p);
}

// round 5
// speedup vs baseline: 1.9683x; 1.3129x over previous
#include <cuda_runtime.h>
#include <cuda_bf16.h>
#include <math.h>
#include <stdint.h>

#define BATCH 8
#define CDIM  256
#define NDIM  4096
#define CQKD  32
#define ATT_SCALE 0.1767766952966369f   // 1/sqrt(32)

// ---------------- scratch (device globals) ------------------------------------
__device__ __nv_bfloat16 g_qh[(size_t)BATCH * NDIM * CQKD];
__device__ __nv_bfloat16 g_ql[(size_t)BATCH * NDIM * CQKD];
__device__ __nv_bfloat16 g_kh[(size_t)BATCH * NDIM * CQKD];
__device__ __nv_bfloat16 g_kl[(size_t)BATCH * NDIM * CQKD];
__device__ __nv_bfloat16 g_vh[(size_t)BATCH * CDIM * NDIM];
__device__ __nv_bfloat16 g_vl[(size_t)BATCH * CDIM * NDIM];
__device__ __nv_bfloat16 g_ah[(size_t)BATCH * NDIM * NDIM];   // attn hi
__device__ __nv_bfloat16 g_al[(size_t)BATCH * NDIM * NDIM];   // attn lo
__device__ float g_attn_fb[(size_t)BATCH * NDIM * NDIM];      // fallback
__device__ float g_tex_fb[(size_t)BATCH * CDIM * NDIM];       // fallback

// =============================== PTX helpers ==================================
__device__ __forceinline__ uint32_t smem_u32(const void* p) {
    uint32_t a;
    asm("{ .reg .u64 t; cvta.to.shared.u64 t, %1; cvt.u32.u64 %0, t; }"
        : "=r"(a) : "l"(p));
    return a;
}
__device__ __forceinline__ void cp16(uint32_t dst, const void* src) {
    asm volatile("cp.async.cg.shared.global [%0], [%1], 16;" :: "r"(dst), "l"(src) : "memory");
}
#define CP_COMMIT() asm volatile("cp.async.commit_group;" ::: "memory")
#define CP_WAIT2()  asm volatile("cp.async.wait_group 2;"  ::: "memory")
#define CP_WAIT0()  asm volatile("cp.async.wait_group 0;"  ::: "memory")

__device__ __forceinline__ void mma_bf16(float* c, const uint32_t* a, const uint32_t* b) {
    asm volatile(
        "mma.sync.aligned.m16n8k16.row.col.f32.bf16.bf16.f32 "
        "{%0,%1,%2,%3}, {%4,%5,%6,%7}, {%8,%9}, {%0,%1,%2,%3};"
        : "+f"(c[0]), "+f"(c[1]), "+f"(c[2]), "+f"(c[3])
        : "r"(a[0]), "r"(a[1]), "r"(a[2]), "r"(a[3]), "r"(b[0]), "r"(b[1]));
}
__device__ __forceinline__ uint32_t bfpack(float x, float y) {
    __nv_bfloat162 h = __floats2bfloat162_rn(x, y);
    return *(uint32_t*)&h;
}
__device__ __forceinline__ void split2(float x, float y, uint32_t& hi, uint32_t& lo) {
    __nv_bfloat16 hx = __float2bfloat16(x);
    __nv_bfloat16 hy = __float2bfloat16(y);
    float lx = x - __bfloat162float(hx);
    float ly = y - __bfloat162float(hy);
    __nv_bfloat162 hp; hp.x = hx; hp.y = hy;
    hi = *(uint32_t*)&hp;
    lo = bfpack(lx, ly);
}

// ---------------- q / k projection -> bf16 hi/lo planes -----------------------
__global__ void proj_small_kernel(const float* __restrict__ X,
                                  const float* __restrict__ W,
                                  const float* __restrict__ bias,
                                  __nv_bfloat16* __restrict__ YH,
                                  __nv_bfloat16* __restrict__ YL)
{
    __shared__ float Ws[CQKD * CDIM];
    int tid = threadIdx.x;
    for (int i = tid; i < CQKD * CDIM; i += 256) Ws[i] = W[i];
    __syncthreads();

    int b = blockIdx.y;
    int n = blockIdx.x * 256 + tid;
    const float* Xp = X + (size_t)b * CDIM * NDIM + n;

    float acc[CQKD];
#pragma unroll
    for (int o = 0; o < CQKD; o++) acc[o] = bias[o];

    for (int c = 0; c < CDIM; c++) {
        float x = Xp[(size_t)c * NDIM];
#pragma unroll
        for (int o = 0; o < CQKD; o++) acc[o] += x * Ws[o * CDIM + c];
    }
    size_t base = ((size_t)b * NDIM + n) * CQKD;
    uint32_t* ph = (uint32_t*)(YH + base);
    uint32_t* pl = (uint32_t*)(YL + base);
#pragma unroll
    for (int o = 0; o < CQKD; o += 2) {
        uint32_t hi, lo;
        split2(acc[o], acc[o + 1], hi, lo);
        ph[o >> 1] = hi; pl[o >> 1] = lo;
    }
}

// ---------------- v projection -> bf16 hi/lo planes ---------------------------
__global__ void proj_v_kernel(const float* __restrict__ X,
                              const float* __restrict__ Wv,
                              const float* __restrict__ bv,
                              __nv_bfloat16* __restrict__ VH,
                              __nv_bfloat16* __restrict__ VL)
{
    __shared__ float Ws[32 * CDIM];
    int tid = threadIdx.x;
    int c0 = blockIdx.y * 32;
    for (int i = tid; i < 32 * CDIM; i += 256) Ws[i] = Wv[(size_t)c0 * CDIM + i];
    __syncthreads();

    int b = blockIdx.z;
    int n = blockIdx.x * 256 + tid;
    const float* Xp = X + (size_t)b * CDIM * NDIM + n;

    float acc[32];
#pragma unroll
    for (int i = 0; i < 32; i++) acc[i] = bv[c0 + i];

    for (int c = 0; c < CDIM; c++) {
        float x = Xp[(size_t)c * NDIM];
#pragma unroll
        for (int i = 0; i < 32; i++) acc[i] += x * Ws[i * CDIM + c];
    }
    size_t base = ((size_t)b * CDIM + c0) * NDIM + n;
#pragma unroll
    for (int i = 0; i < 32; i++) {
        float x = acc[i];
        __nv_bfloat16 h = __float2bfloat16(x);
        VH[base + (size_t)i * NDIM] = h;
        VL[base + (size_t)i * NDIM] = __float2bfloat16(x - __bfloat162float(h));
    }
}

// ============== energy via 3xBF16 mma: E = SCALE * q . k^T ====================
// CTA 128(m) x 128(n), K=32 single chunk; 8 warps of 64x32.
#define EP 40                          // bf16 pitch (80 bytes)
#define EPLANE (128 * EP * 2)          // 10240 bytes per plane

__global__ void __launch_bounds__(256, 1)
energy_mma_kernel(const __nv_bfloat16* __restrict__ QH,
                  const __nv_bfloat16* __restrict__ QL,
                  const __nv_bfloat16* __restrict__ KH,
                  const __nv_bfloat16* __restrict__ KL,
                  float* __restrict__ E)
{
    __shared__ __align__(16) char sm[4 * EPLANE];
    uint32_t sb = smem_u32(sm);
    int tid = threadIdx.x;
    int wid = tid >> 5, lid = tid & 31;
    int g = lid >> 2, t = lid & 3;
    int wm = wid & 1, wn = wid >> 1;

    int b  = blockIdx.z;
    int m0 = blockIdx.y * 128;
    int n0 = blockIdx.x * 128;

    int row  = tid >> 1;
    int half = tid & 1;
    const __nv_bfloat16* srcs[4] = {
        QH + ((size_t)b * NDIM + m0 + row) * CQKD + half * 16,
        QL + ((size_t)b * NDIM + m0 + row) * CQKD + half * 16,
        KH + ((size_t)b * NDIM + n0 + row) * CQKD + half * 16,
        KL + ((size_t)b * NDIM + n0 + row) * CQKD + half * 16 };
#pragma unroll
    for (int p = 0; p < 4; p++) {
        uint32_t dst = sb + p * EPLANE + (uint32_t)row * (EP * 2) + half * 32;
        cp16(dst, srcs[p]);
        cp16(dst + 16, srcs[p] + 8);
    }
    CP_COMMIT(); CP_WAIT0();
    __syncthreads();

    float acc[4][4][4];
#pragma unroll
    for (int mt = 0; mt < 4; mt++)
#pragma unroll
        for (int nt = 0; nt < 4; nt++)
#pragma unroll
            for (int q = 0; q < 4; q++) acc[mt][nt][q] = 0.f;

#pragma unroll
    for (int ks = 0; ks < 2; ks++) {
        uint32_t ah[4][4], al[4][4];
#pragma unroll
        for (int mt = 0; mt < 4; mt++) {
            int r0 = wm * 64 + mt * 16 + g;
            uint32_t o0 = (uint32_t)r0 * 80 + ks * 32 + t * 4;
            uint32_t o1 = (uint32_t)(r0 + 8) * 80 + ks * 32 + t * 4;
            ah[mt][0] = *(const uint32_t*)(sm + o0);
            ah[mt][1] = *(const uint32_t*)(sm + o1);
            ah[mt][2] = *(const uint32_t*)(sm + o0 + 16);
            ah[mt][3] = *(const uint32_t*)(sm + o1 + 16);
            al[mt][0] = *(const uint32_t*)(sm + EPLANE + o0);
            al[mt][1] = *(const uint32_t*)(sm + EPLANE + o1);
            al[mt][2] = *(const uint32_t*)(sm + EPLANE + o0 + 16);
            al[mt][3] = *(const uint32_t*)(sm + EPLANE + o1 + 16);
        }
        uint32_t bh[4][2], bl[4][2];
#pragma unroll
        for (int nt = 0; nt < 4; nt++) {
            int nr = wn * 32 + nt * 8 + g;
            uint32_t ob = (uint32_t)nr * 80 + ks * 32 + t * 4;
            bh[nt][0] = *(const uint32_t*)(sm + 2 * EPLANE + ob);
            bh[nt][1] = *(const uint32_t*)(sm + 2 * EPLANE + ob + 16);
            bl[nt][0] = *(const uint32_t*)(sm + 3 * EPLANE + ob);
            bl[nt][1] = *(const uint32_t*)(sm + 3 * EPLANE + ob + 16);
        }
#pragma unroll
        for (int mt = 0; mt < 4; mt++)
#pragma unroll
            for (int nt = 0; nt < 4; nt++) {
                mma_bf16(acc[mt][nt], ah[mt], bh[nt]);
                mma_bf16(acc[mt][nt], ah[mt], bl[nt]);
                mma_bf16(acc[mt][nt], al[mt], bh[nt]);
            }
    }

#pragma unroll
    for (int mt = 0; mt < 4; mt++) {
        int r0 = m0 + wm * 64 + mt * 16 + g;
#pragma unroll
        for (int nt = 0; nt < 4; nt++) {
            int col = n0 + wn * 32 + nt * 8 + 2 * t;
            size_t off0 = ((size_t)b * NDIM + r0) * NDIM + col;
            size_t off1 = ((size_t)b * NDIM + r0 + 8) * NDIM + col;
            float2 e0 = {acc[mt][nt][0] * ATT_SCALE, acc[mt][nt][1] * ATT_SCALE};
            float2 e1 = {acc[mt][nt][2] * ATT_SCALE, acc[mt][nt][3] * ATT_SCALE};
            *(float2*)(E + off0) = e0;
            *(float2*)(E + off1) = e1;
        }
    }
}

// ---------------- softmax: in-place fp32 + bf16 hi/lo planes ------------------
__global__ void softmax_kernel(float* __restrict__ A,
                               __nv_bfloat16* __restrict__ AH,
                               __nv_bfloat16* __restrict__ AL)
{
    __shared__ float smax[8];
    __shared__ float ssum[8];
    size_t base = (size_t)blockIdx.x * NDIM;
    int tid = threadIdx.x;

    float4 v[4];
    float mx = -3.4e38f;
#pragma unroll
    for (int g = 0; g < 4; g++) {
        v[g] = *(const float4*)(A + base + (size_t)(g * 256 + tid) * 4);
        mx = fmaxf(mx, fmaxf(fmaxf(v[g].x, v[g].y), fmaxf(v[g].z, v[g].w)));
    }
#pragma unroll
    for (int o = 16; o > 0; o >>= 1) mx = fmaxf(mx, __shfl_xor_sync(0xffffffffu, mx, o));
    if ((tid & 31) == 0) smax[tid >> 5] = mx;
    __syncthreads();
    mx = smax[0];
#pragma unroll
    for (int w = 1; w < 8; w++) mx = fmaxf(mx, smax[w]);

    float s = 0.f;
#pragma unroll
    for (int g = 0; g < 4; g++) {
        v[g].x = __expf(v[g].x - mx); v[g].y = __expf(v[g].y - mx);
        v[g].z = __expf(v[g].z - mx); v[g].w = __expf(v[g].w - mx);
        s += v[g].x + v[g].y + v[g].z + v[g].w;
    }
#pragma unroll
    for (int o = 16; o > 0; o >>= 1) s += __shfl_xor_sync(0xffffffffu, s, o);
    if ((tid & 31) == 0) ssum[tid >> 5] = s;
    __syncthreads();
    s = 0.f;
#pragma unroll
    for (int w = 0; w < 8; w++) s += ssum[w];

    float inv = 1.0f / s;
#pragma unroll
    for (int g = 0; g < 4; g++) {
        v[g].x *= inv; v[g].y *= inv; v[g].z *= inv; v[g].w *= inv;
        size_t eoff = base + (size_t)(g * 256 + tid) * 4;
        *(float4*)(A + eoff) = v[g];
        uint32_t h0, l0, h1, l1;
        split2(v[g].x, v[g].y, h0, l0);
        split2(v[g].z, v[g].w, h1, l1);
        uint32_t* ph = (uint32_t*)(AH + eoff);
        uint32_t* pl = (uint32_t*)(AL + eoff);
        ph[0] = h0; ph[1] = h1;
        pl[0] = l0; pl[1] = l1;
    }
}

// ============== texture GEMM via 3xBF16 mma ====================================
// tex[b,c,m] = sum_n V[b,c,n] * attn[b,m,n];  out = tex + sketches
// CTA 128(c) x 128(m), K chunks of 32; 8 warps of 64x32; 4-stage cp.async.
#define XSTAGE_BYTES (4 * EPLANE)       // AH, AL, BH, BL -> 40960
#define XSTAGES 4
#define XSMEM_BYTES (XSTAGES * XSTAGE_BYTES)   // 163840
#define XNCH (NDIM / 32)                // 128

__device__ __forceinline__ void x_load_chunk(int j, uint32_t sb_base, int tid,
                                             const __nv_bfloat16* VHb, const __nv_bfloat16* VLb,
                                             const __nv_bfloat16* AHb, const __nv_bfloat16* ALb)
{
    uint32_t sb = sb_base + (uint32_t)(j & (XSTAGES - 1)) * XSTAGE_BYTES;
    int row  = tid >> 1;
    int half = tid & 1;
    int kt = j * 32;

    const __nv_bfloat16* srcs[4] = {
        VHb + (size_t)row * NDIM + kt + half * 16,
        VLb + (size_t)row * NDIM + kt + half * 16,
        AHb + (size_t)row * NDIM + kt + half * 16,
        ALb + (size_t)row * NDIM + kt + half * 16 };
#pragma unroll
    for (int p = 0; p < 4; p++) {
        uint32_t dst = sb + p * EPLANE + (uint32_t)row * 80 + half * 32;
        cp16(dst, srcs[p]);
        cp16(dst + 16, srcs[p] + 8);
    }
}

__global__ void __launch_bounds__(256, 1)
texture_mma_kernel(const __nv_bfloat16* __restrict__ VH,
                   const __nv_bfloat16* __restrict__ VL,
                   const __nv_bfloat16* __restrict__ AH,
                   const __nv_bfloat16* __restrict__ AL,
                   const float* __restrict__ SK,
                   float* __restrict__ TEX,
                   float* __restrict__ OUT)
{
    extern __shared__ char smem[];
    uint32_t sb_base = smem_u32(smem);
    int tid = threadIdx.x;
    int wid = tid >> 5, lid = tid & 31;
    int g = lid >> 2, t = lid & 3;
    int wm = wid & 1, wn = wid >> 1;

    int b  = blockIdx.z;
    int i0 = blockIdx.y * 128;
    int j0 = blockIdx.x * 128;

    const __nv_bfloat16* VHb = VH + ((size_t)b * CDIM + i0) * NDIM;
    const __nv_bfloat16* VLb = VL + ((size_t)b * CDIM + i0) * NDIM;
    const __nv_bfloat16* AHb = AH + ((size_t)b * NDIM + j0) * NDIM;
    const __nv_bfloat16* ALb = AL + ((size_t)b * NDIM + j0) * NDIM;

    float acc[4][4][4];
#pragma unroll
    for (int mt = 0; mt < 4; mt++)
#pragma unroll
        for (int nt = 0; nt < 4; nt++)
#pragma unroll
            for (int q = 0; q < 4; q++) acc[mt][nt][q] = 0.f;

    x_load_chunk(0, sb_base, tid, VHb, VLb, AHb, ALb); CP_COMMIT();
    x_load_chunk(1, sb_base, tid, VHb, VLb, AHb, ALb); CP_COMMIT();
    x_load_chunk(2, sb_base, tid, VHb, VLb, AHb, ALb); CP_COMMIT();

    for (int i = 0; i < XNCH; i++) {
        CP_WAIT2();
        __syncthreads();
        if (i + 3 < XNCH) x_load_chunk(i + 3, sb_base, tid, VHb, VLb, AHb, ALb);
        CP_COMMIT();

        const char* sA = smem + (size_t)(i & (XSTAGES - 1)) * XSTAGE_BYTES;
        const char* sAl = sA + EPLANE;
        const char* sBh = sA + 2 * EPLANE;
        const char* sBl = sA + 3 * EPLANE;

#pragma unroll
        for (int ks = 0; ks < 2; ks++) {
            uint32_t ah[4][4], al[4][4];
#pragma unroll
            for (int mt = 0; mt < 4; mt++) {
                int r0 = wm * 64 + mt * 16 + g;
                uint32_t o0 = (uint32_t)r0 * 80 + ks * 32 + t * 4;
                uint32_t o1 = (uint32_t)(r0 + 8) * 80 + ks * 32 + t * 4;
                ah[mt][0] = *(const uint32_t*)(sA + o0);
                ah[mt][1] = *(const uint32_t*)(sA + o1);
                ah[mt][2] = *(const uint32_t*)(sA + o0 + 16);
                ah[mt][3] = *(const uint32_t*)(sA + o1 + 16);
                al[mt][0] = *(const uint32_t*)(sAl + o0);
                al[mt][1] = *(const uint32_t*)(sAl + o1);
                al[mt][2] = *(const uint32_t*)(sAl + o0 + 16);
                al[mt][3] = *(const uint32_t*)(sAl + o1 + 16);
            }
            uint32_t bh[4][2], bl[4][2];
#pragma unroll
            for (int nt = 0; nt < 4; nt++) {
                int nr = wn * 32 + nt * 8 + g;
                uint32_t ob = (uint32_t)nr * 80 + ks * 32 + t * 4;
                bh[nt][0] = *(const uint32_t*)(sBh + ob);
                bh[nt][1] = *(const uint32_t*)(sBh + ob + 16);
                bl[nt][0] = *(const uint32_t*)(sBl + ob);
                bl[nt][1] = *(const uint32_t*)(sBl + ob + 16);
            }
#pragma unroll
            for (int mt = 0; mt < 4; mt++)
#pragma unroll
                for (int nt = 0; nt < 4; nt++) {
                    mma_bf16(acc[mt][nt], ah[mt], bh[nt]);
                    mma_bf16(acc[mt][nt], ah[mt], bl[nt]);
                    mma_bf16(acc[mt][nt], al[mt], bh[nt]);
                }
        }
        __syncthreads();
    }
    CP_WAIT0();

#pragma unroll
    for (int mt = 0; mt < 4; mt++) {
        int r0 = i0 + wm * 64 + mt * 16 + g;
#pragma unroll
        for (int nt = 0; nt < 4; nt++) {
            int col = j0 + wn * 32 + nt * 8 + 2 * t;
            size_t off0 = ((size_t)b * CDIM + r0) * NDIM + col;
            size_t off1 = ((size_t)b * CDIM + r0 + 8) * NDIM + col;
            float2 t0 = {acc[mt][nt][0], acc[mt][nt][1]};
            float2 t1 = {acc[mt][nt][2], acc[mt][nt][3]};
            float2 s0 = *(const float2*)(SK + off0);
            float2 s1 = *(const float2*)(SK + off1);
            *(float2*)(TEX + off0) = t0;
            *(float2*)(TEX + off1) = t1;
            float2 o0 = {t0.x + s0.x, t0.y + s0.y};
            float2 o1 = {t1.x + s1.x, t1.y + s1.y};
            *(float2*)(OUT + off0) = o0;
            *(float2*)(OUT + off1) = o1;
        }
    }
}

// ---------------- launch -------------------------------------------------------
extern "C" void kernel_launch(void* const* d_in, const int* in_sizes, int n_in,
                              void* d_out, int out_size)
{
    const float* sk = (const float*)d_in[0];
    const float* ex = (const float*)d_in[1];
    const float* Wq = (const float*)d_in[2];
    const float* bq = (const float*)d_in[3];
    const float* Wk = (const float*)d_in[4];
    const float* bk = (const float*)d_in[5];
    const float* Wv = (const float*)d_in[6];
    const float* bv = (const float*)d_in[7];

    const size_t BCN = (size_t)BATCH * CDIM * NDIM;
    const size_t BNN = (size_t)BATCH * NDIM * NDIM;

    float* out_p = (float*)d_out;
    float* tex_p;
    float* attn_p;

    if ((size_t)(unsigned)out_size >= 2 * BCN + BNN) {
        tex_p  = out_p + BCN;
        attn_p = out_p + 2 * BCN;
    } else {
        void* p;
        cudaGetSymbolAddress(&p, g_tex_fb);  tex_p  = (float*)p;
        cudaGetSymbolAddress(&p, g_attn_fb); attn_p = (float*)p;
    }

    __nv_bfloat16 *qh, *ql, *kh, *kl, *vh, *vl, *ah, *al;
    { void* p;
      cudaGetSymbolAddress(&p, g_qh); qh = (__nv_bfloat16*)p;
      cudaGetSymbolAddress(&p, g_ql); ql = (__nv_bfloat16*)p;
      cudaGetSymbolAddress(&p, g_kh); kh = (__nv_bfloat16*)p;
      cudaGetSymbolAddress(&p, g_kl); kl = (__nv_bfloat16*)p;
      cudaGetSymbolAddress(&p, g_vh); vh = (__nv_bfloat16*)p;
      cudaGetSymbolAddress(&p, g_vl); vl = (__nv_bfloat16*)p;
      cudaGetSymbolAddress(&p, g_ah); ah = (__nv_bfloat16*)p;
      cudaGetSymbolAddress(&p, g_al); al = (__nv_bfloat16*)p; }

    // 1) q, k projections -> bf16 hi/lo
    dim3 gproj(NDIM / 256, BATCH);
    proj_small_kernel<<<gproj, 256>>>(sk, Wq, bq, qh, ql);
    proj_small_kernel<<<gproj, 256>>>(ex, Wk, bk, kh, kl);

    // 2) v projection -> bf16 hi/lo
    dim3 gv(NDIM / 256, CDIM / 32, BATCH);
    proj_v_kernel<<<gv, 256>>>(ex, Wv, bv, vh, vl);

    // 3) energy via mma -> raw scores into attention buffer
    dim3 ge(NDIM / 128, NDIM / 128, BATCH);
    energy_mma_kernel<<<ge, 256>>>(qh, ql, kh, kl, attn_p);

    // 4) softmax in place + bf16 hi/lo planes
    softmax_kernel<<<BATCH * NDIM, 256>>>(attn_p, ah, al);

    // 5) texture GEMM via mma + residual epilogue
    static int smem_set = 0;
    if (!smem_set) {
        cudaFuncSetAttribute(texture_mma_kernel,
                             cudaFuncAttributeMaxDynamicSharedMemorySize, XSMEM_BYTES);
        smem_set = 1;
    }
    dim3 gt(NDIM / 128, CDIM / 128, BATCH);
    texture_mma_kernel<<<gt, 256, XSMEM_BYTES>>>(vh, vl, ah, al, sk, tex_p, out_p);
}

// round 6
// speedup vs baseline: 2.7895x; 1.4172x over previous
#include <cuda_runtime.h>
#include <cuda_bf16.h>
#include <cuda_fp16.h>
#include <math.h>
#include <stdint.h>

#define BATCH 8
#define CDIM  256
#define NDIM  4096
#define CQKD  32
#define ATT_SCALE 0.1767766952966369f   // 1/sqrt(32)

// ---------------- scratch (device globals) ------------------------------------
__device__ __nv_bfloat16 g_qh[(size_t)BATCH * NDIM * CQKD];
__device__ __nv_bfloat16 g_ql[(size_t)BATCH * NDIM * CQKD];
__device__ __nv_bfloat16 g_kh[(size_t)BATCH * NDIM * CQKD];
__device__ __nv_bfloat16 g_kl[(size_t)BATCH * NDIM * CQKD];
__device__ __half        g_vh[(size_t)BATCH * CDIM * NDIM];   // V fp16
__device__ __half        g_ah[(size_t)BATCH * NDIM * NDIM];   // attn fp16
__device__ float g_attn_fb[(size_t)BATCH * NDIM * NDIM];      // fallback
__device__ float g_tex_fb[(size_t)BATCH * CDIM * NDIM];       // fallback

// =============================== PTX helpers ==================================
__device__ __forceinline__ uint32_t smem_u32(const void* p) {
    uint32_t a;
    asm("{ .reg .u64 t; cvta.to.shared.u64 t, %1; cvt.u32.u64 %0, t; }"
        : "=r"(a) : "l"(p));
    return a;
}
__device__ __forceinline__ void cp16(uint32_t dst, const void* src) {
    asm volatile("cp.async.cg.shared.global [%0], [%1], 16;" :: "r"(dst), "l"(src) : "memory");
}
#define CP_COMMIT() asm volatile("cp.async.commit_group;" ::: "memory")
#define CP_WAIT2()  asm volatile("cp.async.wait_group 2;"  ::: "memory")
#define CP_WAIT0()  asm volatile("cp.async.wait_group 0;"  ::: "memory")

__device__ __forceinline__ void mma_bf16(float* c, const uint32_t* a, const uint32_t* b) {
    asm volatile(
        "mma.sync.aligned.m16n8k16.row.col.f32.bf16.bf16.f32 "
        "{%0,%1,%2,%3}, {%4,%5,%6,%7}, {%8,%9}, {%0,%1,%2,%3};"
        : "+f"(c[0]), "+f"(c[1]), "+f"(c[2]), "+f"(c[3])
        : "r"(a[0]), "r"(a[1]), "r"(a[2]), "r"(a[3]), "r"(b[0]), "r"(b[1]));
}
__device__ __forceinline__ void mma_f16(float* c, const uint32_t* a, const uint32_t* b) {
    asm volatile(
        "mma.sync.aligned.m16n8k16.row.col.f32.f16.f16.f32 "
        "{%0,%1,%2,%3}, {%4,%5,%6,%7}, {%8,%9}, {%0,%1,%2,%3};"
        : "+f"(c[0]), "+f"(c[1]), "+f"(c[2]), "+f"(c[3])
        : "r"(a[0]), "r"(a[1]), "r"(a[2]), "r"(a[3]), "r"(b[0]), "r"(b[1]));
}
__device__ __forceinline__ uint32_t bfpack(float x, float y) {
    __nv_bfloat162 h = __floats2bfloat162_rn(x, y);
    return *(uint32_t*)&h;
}
__device__ __forceinline__ void split2(float x, float y, uint32_t& hi, uint32_t& lo) {
    __nv_bfloat16 hx = __float2bfloat16(x);
    __nv_bfloat16 hy = __float2bfloat16(y);
    float lx = x - __bfloat162float(hx);
    float ly = y - __bfloat162float(hy);
    __nv_bfloat162 hp; hp.x = hx; hp.y = hy;
    hi = *(uint32_t*)&hp;
    lo = bfpack(lx, ly);
}

// ---------------- q / k projection -> bf16 hi/lo planes -----------------------
__global__ void proj_small_kernel(const float* __restrict__ X,
                                  const float* __restrict__ W,
                                  const float* __restrict__ bias,
                                  __nv_bfloat16* __restrict__ YH,
                                  __nv_bfloat16* __restrict__ YL)
{
    __shared__ float Ws[CQKD * CDIM];
    int tid = threadIdx.x;
    for (int i = tid; i < CQKD * CDIM; i += 256) Ws[i] = W[i];
    __syncthreads();

    int b = blockIdx.y;
    int n = blockIdx.x * 256 + tid;
    const float* Xp = X + (size_t)b * CDIM * NDIM + n;

    float acc[CQKD];
#pragma unroll
    for (int o = 0; o < CQKD; o++) acc[o] = bias[o];

    for (int c = 0; c < CDIM; c++) {
        float x = Xp[(size_t)c * NDIM];
#pragma unroll
        for (int o = 0; o < CQKD; o++) acc[o] += x * Ws[o * CDIM + c];
    }
    size_t base = ((size_t)b * NDIM + n) * CQKD;
    uint32_t* ph = (uint32_t*)(YH + base);
    uint32_t* pl = (uint32_t*)(YL + base);
#pragma unroll
    for (int o = 0; o < CQKD; o += 2) {
        uint32_t hi, lo;
        split2(acc[o], acc[o + 1], hi, lo);
        ph[o >> 1] = hi; pl[o >> 1] = lo;
    }
}

// ---------------- v projection -> fp16 plane ----------------------------------
__global__ void proj_v_kernel(const float* __restrict__ X,
                              const float* __restrict__ Wv,
                              const float* __restrict__ bv,
                              __half* __restrict__ VH)
{
    __shared__ float Ws[32 * CDIM];
    int tid = threadIdx.x;
    int c0 = blockIdx.y * 32;
    for (int i = tid; i < 32 * CDIM; i += 256) Ws[i] = Wv[(size_t)c0 * CDIM + i];
    __syncthreads();

    int b = blockIdx.z;
    int n = blockIdx.x * 256 + tid;
    const float* Xp = X + (size_t)b * CDIM * NDIM + n;

    float acc[32];
#pragma unroll
    for (int i = 0; i < 32; i++) acc[i] = bv[c0 + i];

    for (int c = 0; c < CDIM; c++) {
        float x = Xp[(size_t)c * NDIM];
#pragma unroll
        for (int i = 0; i < 32; i++) acc[i] += x * Ws[i * CDIM + c];
    }
    size_t base = ((size_t)b * CDIM + c0) * NDIM + n;
#pragma unroll
    for (int i = 0; i < 32; i++)
        VH[base + (size_t)i * NDIM] = __float2half_rn(acc[i]);
}

// ============== energy via 3xBF16 mma: E = SCALE * q . k^T ====================
#define EP 40                          // element pitch (80 bytes)
#define EPLANE (128 * EP * 2)          // 10240 bytes per plane

__global__ void __launch_bounds__(256, 1)
energy_mma_kernel(const __nv_bfloat16* __restrict__ QH,
                  const __nv_bfloat16* __restrict__ QL,
                  const __nv_bfloat16* __restrict__ KH,
                  const __nv_bfloat16* __restrict__ KL,
                  float* __restrict__ E)
{
    __shared__ __align__(16) char sm[4 * EPLANE];
    uint32_t sb = smem_u32(sm);
    int tid = threadIdx.x;
    int wid = tid >> 5, lid = tid & 31;
    int g = lid >> 2, t = lid & 3;
    int wm = wid & 1, wn = wid >> 1;

    int b  = blockIdx.z;
    int m0 = blockIdx.y * 128;
    int n0 = blockIdx.x * 128;

    int row  = tid >> 1;
    int half = tid & 1;
    const __nv_bfloat16* srcs[4] = {
        QH + ((size_t)b * NDIM + m0 + row) * CQKD + half * 16,
        QL + ((size_t)b * NDIM + m0 + row) * CQKD + half * 16,
        KH + ((size_t)b * NDIM + n0 + row) * CQKD + half * 16,
        KL + ((size_t)b * NDIM + n0 + row) * CQKD + half * 16 };
#pragma unroll
    for (int p = 0; p < 4; p++) {
        uint32_t dst = sb + p * EPLANE + (uint32_t)row * (EP * 2) + half * 32;
        cp16(dst, srcs[p]);
        cp16(dst + 16, srcs[p] + 8);
    }
    CP_COMMIT(); CP_WAIT0();
    __syncthreads();

    float acc[4][4][4];
#pragma unroll
    for (int mt = 0; mt < 4; mt++)
#pragma unroll
        for (int nt = 0; nt < 4; nt++)
#pragma unroll
            for (int q = 0; q < 4; q++) acc[mt][nt][q] = 0.f;

#pragma unroll
    for (int ks = 0; ks < 2; ks++) {
        uint32_t ah[4][4], al[4][4];
#pragma unroll
        for (int mt = 0; mt < 4; mt++) {
            int r0 = wm * 64 + mt * 16 + g;
            uint32_t o0 = (uint32_t)r0 * 80 + ks * 32 + t * 4;
            uint32_t o1 = (uint32_t)(r0 + 8) * 80 + ks * 32 + t * 4;
            ah[mt][0] = *(const uint32_t*)(sm + o0);
            ah[mt][1] = *(const uint32_t*)(sm + o1);
            ah[mt][2] = *(const uint32_t*)(sm + o0 + 16);
            ah[mt][3] = *(const uint32_t*)(sm + o1 + 16);
            al[mt][0] = *(const uint32_t*)(sm + EPLANE + o0);
            al[mt][1] = *(const uint32_t*)(sm + EPLANE + o1);
            al[mt][2] = *(const uint32_t*)(sm + EPLANE + o0 + 16);
            al[mt][3] = *(const uint32_t*)(sm + EPLANE + o1 + 16);
        }
        uint32_t bh[4][2], bl[4][2];
#pragma unroll
        for (int nt = 0; nt < 4; nt++) {
            int nr = wn * 32 + nt * 8 + g;
            uint32_t ob = (uint32_t)nr * 80 + ks * 32 + t * 4;
            bh[nt][0] = *(const uint32_t*)(sm + 2 * EPLANE + ob);
            bh[nt][1] = *(const uint32_t*)(sm + 2 * EPLANE + ob + 16);
            bl[nt][0] = *(const uint32_t*)(sm + 3 * EPLANE + ob);
            bl[nt][1] = *(const uint32_t*)(sm + 3 * EPLANE + ob + 16);
        }
#pragma unroll
        for (int mt = 0; mt < 4; mt++)
#pragma unroll
            for (int nt = 0; nt < 4; nt++) {
                mma_bf16(acc[mt][nt], ah[mt], bh[nt]);
                mma_bf16(acc[mt][nt], ah[mt], bl[nt]);
                mma_bf16(acc[mt][nt], al[mt], bh[nt]);
            }
    }

#pragma unroll
    for (int mt = 0; mt < 4; mt++) {
        int r0 = m0 + wm * 64 + mt * 16 + g;
#pragma unroll
        for (int nt = 0; nt < 4; nt++) {
            int col = n0 + wn * 32 + nt * 8 + 2 * t;
            size_t off0 = ((size_t)b * NDIM + r0) * NDIM + col;
            size_t off1 = ((size_t)b * NDIM + r0 + 8) * NDIM + col;
            float2 e0 = {acc[mt][nt][0] * ATT_SCALE, acc[mt][nt][1] * ATT_SCALE};
            float2 e1 = {acc[mt][nt][2] * ATT_SCALE, acc[mt][nt][3] * ATT_SCALE};
            *(float2*)(E + off0) = e0;
            *(float2*)(E + off1) = e1;
        }
    }
}

// ---------------- softmax: in-place fp32 + fp16 plane -------------------------
__global__ void softmax_kernel(float* __restrict__ A,
                               __half* __restrict__ AH)
{
    __shared__ float smax[8];
    __shared__ float ssum[8];
    size_t base = (size_t)blockIdx.x * NDIM;
    int tid = threadIdx.x;

    float4 v[4];
    float mx = -3.4e38f;
#pragma unroll
    for (int g = 0; g < 4; g++) {
        v[g] = *(const float4*)(A + base + (size_t)(g * 256 + tid) * 4);
        mx = fmaxf(mx, fmaxf(fmaxf(v[g].x, v[g].y), fmaxf(v[g].z, v[g].w)));
    }
#pragma unroll
    for (int o = 16; o > 0; o >>= 1) mx = fmaxf(mx, __shfl_xor_sync(0xffffffffu, mx, o));
    if ((tid & 31) == 0) smax[tid >> 5] = mx;
    __syncthreads();
    mx = smax[0];
#pragma unroll
    for (int w = 1; w < 8; w++) mx = fmaxf(mx, smax[w]);

    float s = 0.f;
#pragma unroll
    for (int g = 0; g < 4; g++) {
        v[g].x = __expf(v[g].x - mx); v[g].y = __expf(v[g].y - mx);
        v[g].z = __expf(v[g].z - mx); v[g].w = __expf(v[g].w - mx);
        s += v[g].x + v[g].y + v[g].z + v[g].w;
    }
#pragma unroll
    for (int o = 16; o > 0; o >>= 1) s += __shfl_xor_sync(0xffffffffu, s, o);
    if ((tid & 31) == 0) ssum[tid >> 5] = s;
    __syncthreads();
    s = 0.f;
#pragma unroll
    for (int w = 0; w < 8; w++) s += ssum[w];

    float inv = 1.0f / s;
#pragma unroll
    for (int g = 0; g < 4; g++) {
        v[g].x *= inv; v[g].y *= inv; v[g].z *= inv; v[g].w *= inv;
        size_t eoff = base + (size_t)(g * 256 + tid) * 4;
        *(float4*)(A + eoff) = v[g];
        __half2 h0 = __floats2half2_rn(v[g].x, v[g].y);
        __half2 h1 = __floats2half2_rn(v[g].z, v[g].w);
        uint32_t* ph = (uint32_t*)(AH + eoff);
        ph[0] = *(uint32_t*)&h0;
        ph[1] = *(uint32_t*)&h1;
    }
}

// ============== texture GEMM via single fp16 mma ===============================
// tex[b,c,m] = sum_n V[b,c,n] * attn[b,m,n];  out = tex + sketches
// CTA 128(c) x 128(m), K chunks of 32; 8 warps of 64x32; 4-stage cp.async.
#define XSTAGE_BYTES (2 * EPLANE)       // V plane + A plane -> 20480
#define XSTAGES 4
#define XSMEM_BYTES (XSTAGES * XSTAGE_BYTES)   // 81920
#define XNCH (NDIM / 32)                // 128

__device__ __forceinline__ void x_load_chunk(int j, uint32_t sb_base, int tid,
                                             const __half* VHb, const __half* AHb)
{
    uint32_t sb = sb_base + (uint32_t)(j & (XSTAGES - 1)) * XSTAGE_BYTES;
    int row  = tid >> 1;
    int half = tid & 1;
    int kt = j * 32;

    const __half* s0 = VHb + (size_t)row * NDIM + kt + half * 16;
    const __half* s1 = AHb + (size_t)row * NDIM + kt + half * 16;
    uint32_t d0 = sb + (uint32_t)row * 80 + half * 32;
    uint32_t d1 = d0 + EPLANE;
    cp16(d0, s0); cp16(d0 + 16, s0 + 8);
    cp16(d1, s1); cp16(d1 + 16, s1 + 8);
}

__global__ void __launch_bounds__(256, 2)
texture_mma_kernel(const __half* __restrict__ VH,
                   const __half* __restrict__ AH,
                   const float* __restrict__ SK,
                   float* __restrict__ TEX,
                   float* __restrict__ OUT)
{
    extern __shared__ char smem[];
    uint32_t sb_base = smem_u32(smem);
    int tid = threadIdx.x;
    int wid = tid >> 5, lid = tid & 31;
    int g = lid >> 2, t = lid & 3;
    int wm = wid & 1, wn = wid >> 1;

    int b  = blockIdx.z;
    int i0 = blockIdx.y * 128;
    int j0 = blockIdx.x * 128;

    const __half* VHb = VH + ((size_t)b * CDIM + i0) * NDIM;
    const __half* AHb = AH + ((size_t)b * NDIM + j0) * NDIM;

    float acc[4][4][4];
#pragma unroll
    for (int mt = 0; mt < 4; mt++)
#pragma unroll
        for (int nt = 0; nt < 4; nt++)
#pragma unroll
            for (int q = 0; q < 4; q++) acc[mt][nt][q] = 0.f;

    x_load_chunk(0, sb_base, tid, VHb, AHb); CP_COMMIT();
    x_load_chunk(1, sb_base, tid, VHb, AHb); CP_COMMIT();
    x_load_chunk(2, sb_base, tid, VHb, AHb); CP_COMMIT();

    for (int i = 0; i < XNCH; i++) {
        CP_WAIT2();
        __syncthreads();
        if (i + 3 < XNCH) x_load_chunk(i + 3, sb_base, tid, VHb, AHb);
        CP_COMMIT();

        const char* sA = smem + (size_t)(i & (XSTAGES - 1)) * XSTAGE_BYTES;
        const char* sB = sA + EPLANE;

#pragma unroll
        for (int ks = 0; ks < 2; ks++) {
            uint32_t af[4][4];
#pragma unroll
            for (int mt = 0; mt < 4; mt++) {
                int r0 = wm * 64 + mt * 16 + g;
                uint32_t o0 = (uint32_t)r0 * 80 + ks * 32 + t * 4;
                uint32_t o1 = (uint32_t)(r0 + 8) * 80 + ks * 32 + t * 4;
                af[mt][0] = *(const uint32_t*)(sA + o0);
                af[mt][1] = *(const uint32_t*)(sA + o1);
                af[mt][2] = *(const uint32_t*)(sA + o0 + 16);
                af[mt][3] = *(const uint32_t*)(sA + o1 + 16);
            }
            uint32_t bf[4][2];
#pragma unroll
            for (int nt = 0; nt < 4; nt++) {
                int nr = wn * 32 + nt * 8 + g;
                uint32_t ob = (uint32_t)nr * 80 + ks * 32 + t * 4;
                bf[nt][0] = *(const uint32_t*)(sB + ob);
                bf[nt][1] = *(const uint32_t*)(sB + ob + 16);
            }
#pragma unroll
            for (int mt = 0; mt < 4; mt++)
#pragma unroll
                for (int nt = 0; nt < 4; nt++)
                    mma_f16(acc[mt][nt], af[mt], bf[nt]);
        }
        __syncthreads();
    }
    CP_WAIT0();

#pragma unroll
    for (int mt = 0; mt < 4; mt++) {
        int r0 = i0 + wm * 64 + mt * 16 + g;
#pragma unroll
        for (int nt = 0; nt < 4; nt++) {
            int col = j0 + wn * 32 + nt * 8 + 2 * t;
            size_t off0 = ((size_t)b * CDIM + r0) * NDIM + col;
            size_t off1 = ((size_t)b * CDIM + r0 + 8) * NDIM + col;
            float2 t0 = {acc[mt][nt][0], acc[mt][nt][1]};
            float2 t1 = {acc[mt][nt][2], acc[mt][nt][3]};
            float2 s0 = *(const float2*)(SK + off0);
            float2 s1 = *(const float2*)(SK + off1);
            *(float2*)(TEX + off0) = t0;
            *(float2*)(TEX + off1) = t1;
            float2 o0 = {t0.x + s0.x, t0.y + s0.y};
            float2 o1 = {t1.x + s1.x, t1.y + s1.y};
            *(float2*)(OUT + off0) = o0;
            *(float2*)(OUT + off1) = o1;
        }
    }
}

// ---------------- launch -------------------------------------------------------
extern "C" void kernel_launch(void* const* d_in, const int* in_sizes, int n_in,
                              void* d_out, int out_size)
{
    const float* sk = (const float*)d_in[0];
    const float* ex = (const float*)d_in[1];
    const float* Wq = (const float*)d_in[2];
    const float* bq = (const float*)d_in[3];
    const float* Wk = (const float*)d_in[4];
    const float* bk = (const float*)d_in[5];
    const float* Wv = (const float*)d_in[6];
    const float* bv = (const float*)d_in[7];

    const size_t BCN = (size_t)BATCH * CDIM * NDIM;
    const size_t BNN = (size_t)BATCH * NDIM * NDIM;

    float* out_p = (float*)d_out;
    float* tex_p;
    float* attn_p;

    if ((size_t)(unsigned)out_size >= 2 * BCN + BNN) {
        tex_p  = out_p + BCN;
        attn_p = out_p + 2 * BCN;
    } else {
        void* p;
        cudaGetSymbolAddress(&p, g_tex_fb);  tex_p  = (float*)p;
        cudaGetSymbolAddress(&p, g_attn_fb); attn_p = (float*)p;
    }

    __nv_bfloat16 *qh, *ql, *kh, *kl;
    __half *vh, *ah;
    { void* p;
      cudaGetSymbolAddress(&p, g_qh); qh = (__nv_bfloat16*)p;
      cudaGetSymbolAddress(&p, g_ql); ql = (__nv_bfloat16*)p;
      cudaGetSymbolAddress(&p, g_kh); kh = (__nv_bfloat16*)p;
      cudaGetSymbolAddress(&p, g_kl); kl = (__nv_bfloat16*)p;
      cudaGetSymbolAddress(&p, g_vh); vh = (__half*)p;
      cudaGetSymbolAddress(&p, g_ah); ah = (__half*)p; }

    // 1) q, k projections -> bf16 hi/lo
    dim3 gproj(NDIM / 256, BATCH);
    proj_small_kernel<<<gproj, 256>>>(sk, Wq, bq, qh, ql);
    proj_small_kernel<<<gproj, 256>>>(ex, Wk, bk, kh, kl);

    // 2) v projection -> fp16
    dim3 gv(NDIM / 256, CDIM / 32, BATCH);
    proj_v_kernel<<<gv, 256>>>(ex, Wv, bv, vh);

    // 3) energy via mma -> raw scores into attention buffer
    dim3 ge(NDIM / 128, NDIM / 128, BATCH);
    energy_mma_kernel<<<ge, 256>>>(qh, ql, kh, kl, attn_p);

    // 4) softmax in place + fp16 plane
    softmax_kernel<<<BATCH * NDIM, 256>>>(attn_p, ah);

    // 5) texture GEMM via fp16 mma + residual epilogue
    static int smem_set = 0;
    if (!smem_set) {
        cudaFuncSetAttribute(texture_mma_kernel,
                             cudaFuncAttributeMaxDynamicSharedMemorySize, XSMEM_BYTES);
        smem_set = 1;
    }
    dim3 gt(NDIM / 128, CDIM / 128, BATCH);
    texture_mma_kernel<<<gt, 256, XSMEM_BYTES>>>(vh, ah, sk, tex_p, out_p);
}

// round 7
// speedup vs baseline: 2.9575x; 1.0602x over previous
#include <cuda_runtime.h>
#include <cuda_bf16.h>
#include <cuda_fp16.h>
#include <math.h>
#include <stdint.h>

#define BATCH 8
#define CDIM  256
#define NDIM  4096
#define CQKD  32
#define ATT_SCALE 0.1767766952966369f   // 1/sqrt(32)

// ---------------- scratch (device globals) ------------------------------------
__device__ __nv_bfloat16 g_qh[(size_t)BATCH * NDIM * CQKD];
__device__ __nv_bfloat16 g_ql[(size_t)BATCH * NDIM * CQKD];
__device__ __nv_bfloat16 g_kh[(size_t)BATCH * NDIM * CQKD];
__device__ __nv_bfloat16 g_kl[(size_t)BATCH * NDIM * CQKD];
__device__ __half        g_vh[(size_t)BATCH * CDIM * NDIM];   // V fp16
__device__ __half        g_ah[(size_t)BATCH * NDIM * NDIM];   // attn fp16
__device__ float g_attn_fb[(size_t)BATCH * NDIM * NDIM];      // fallback
__device__ float g_tex_fb[(size_t)BATCH * CDIM * NDIM];       // fallback

// =============================== PTX helpers ==================================
__device__ __forceinline__ uint32_t smem_u32(const void* p) {
    uint32_t a;
    asm("{ .reg .u64 t; cvta.to.shared.u64 t, %1; cvt.u32.u64 %0, t; }"
        : "=r"(a) : "l"(p));
    return a;
}
__device__ __forceinline__ void cp16(uint32_t dst, const void* src) {
    asm volatile("cp.async.cg.shared.global [%0], [%1], 16;" :: "r"(dst), "l"(src) : "memory");
}
#define CP_COMMIT() asm volatile("cp.async.commit_group;" ::: "memory")
#define CP_WAIT2()  asm volatile("cp.async.wait_group 2;"  ::: "memory")
#define CP_WAIT0()  asm volatile("cp.async.wait_group 0;"  ::: "memory")

__device__ __forceinline__ void ldm_x4(uint32_t* r, uint32_t addr) {
    asm volatile("ldmatrix.sync.aligned.m8n8.x4.shared.b16 {%0,%1,%2,%3}, [%4];"
        : "=r"(r[0]), "=r"(r[1]), "=r"(r[2]), "=r"(r[3]) : "r"(addr));
}
__device__ __forceinline__ void mma_bf16(float* c, const uint32_t* a, const uint32_t* b) {
    asm volatile(
        "mma.sync.aligned.m16n8k16.row.col.f32.bf16.bf16.f32 "
        "{%0,%1,%2,%3}, {%4,%5,%6,%7}, {%8,%9}, {%0,%1,%2,%3};"
        : "+f"(c[0]), "+f"(c[1]), "+f"(c[2]), "+f"(c[3])
        : "r"(a[0]), "r"(a[1]), "r"(a[2]), "r"(a[3]), "r"(b[0]), "r"(b[1]));
}
__device__ __forceinline__ void mma_f16(float* c, const uint32_t* a, const uint32_t* b) {
    asm volatile(
        "mma.sync.aligned.m16n8k16.row.col.f32.f16.f16.f32 "
        "{%0,%1,%2,%3}, {%4,%5,%6,%7}, {%8,%9}, {%0,%1,%2,%3};"
        : "+f"(c[0]), "+f"(c[1]), "+f"(c[2]), "+f"(c[3])
        : "r"(a[0]), "r"(a[1]), "r"(a[2]), "r"(a[3]), "r"(b[0]), "r"(b[1]));
}
__device__ __forceinline__ uint32_t bfpack(float x, float y) {
    __nv_bfloat162 h = __floats2bfloat162_rn(x, y);
    return *(uint32_t*)&h;
}
__device__ __forceinline__ void split2(float x, float y, uint32_t& hi, uint32_t& lo) {
    __nv_bfloat16 hx = __float2bfloat16(x);
    __nv_bfloat16 hy = __float2bfloat16(y);
    float lx = x - __bfloat162float(hx);
    float ly = y - __bfloat162float(hy);
    __nv_bfloat162 hp; hp.x = hx; hp.y = hy;
    hi = *(uint32_t*)&hp;
    lo = bfpack(lx, ly);
}

// ---------------- q / k projection -> bf16 hi/lo planes -----------------------
__global__ void proj_small_kernel(const float* __restrict__ X,
                                  const float* __restrict__ W,
                                  const float* __restrict__ bias,
                                  __nv_bfloat16* __restrict__ YH,
                                  __nv_bfloat16* __restrict__ YL)
{
    __shared__ float Ws[CQKD * CDIM];
    int tid = threadIdx.x;
    for (int i = tid; i < CQKD * CDIM; i += 256) Ws[i] = W[i];
    __syncthreads();

    int b = blockIdx.y;
    int n = blockIdx.x * 256 + tid;
    const float* Xp = X + (size_t)b * CDIM * NDIM + n;

    float acc[CQKD];
#pragma unroll
    for (int o = 0; o < CQKD; o++) acc[o] = bias[o];

    for (int c = 0; c < CDIM; c++) {
        float x = Xp[(size_t)c * NDIM];
#pragma unroll
        for (int o = 0; o < CQKD; o++) acc[o] += x * Ws[o * CDIM + c];
    }
    size_t base = ((size_t)b * NDIM + n) * CQKD;
    uint32_t* ph = (uint32_t*)(YH + base);
    uint32_t* pl = (uint32_t*)(YL + base);
#pragma unroll
    for (int o = 0; o < CQKD; o += 2) {
        uint32_t hi, lo;
        split2(acc[o], acc[o + 1], hi, lo);
        ph[o >> 1] = hi; pl[o >> 1] = lo;
    }
}

// ---------------- v projection -> fp16 plane ----------------------------------
__global__ void proj_v_kernel(const float* __restrict__ X,
                              const float* __restrict__ Wv,
                              const float* __restrict__ bv,
                              __half* __restrict__ VH)
{
    __shared__ float Ws[32 * CDIM];
    int tid = threadIdx.x;
    int c0 = blockIdx.y * 32;
    for (int i = tid; i < 32 * CDIM; i += 256) Ws[i] = Wv[(size_t)c0 * CDIM + i];
    __syncthreads();

    int b = blockIdx.z;
    int n = blockIdx.x * 256 + tid;
    const float* Xp = X + (size_t)b * CDIM * NDIM + n;

    float acc[32];
#pragma unroll
    for (int i = 0; i < 32; i++) acc[i] = bv[c0 + i];

    for (int c = 0; c < CDIM; c++) {
        float x = Xp[(size_t)c * NDIM];
#pragma unroll
        for (int i = 0; i < 32; i++) acc[i] += x * Ws[i * CDIM + c];
    }
    size_t base = ((size_t)b * CDIM + c0) * NDIM + n;
#pragma unroll
    for (int i = 0; i < 32; i++)
        VH[base + (size_t)i * NDIM] = __float2half_rn(acc[i]);
}

// ============== energy via 3xBF16 mma: E = SCALE * q . k^T ====================
#define EP 40                          // element pitch (80 bytes)
#define EPLANE (128 * EP * 2)          // 10240 bytes per plane

__global__ void __launch_bounds__(256, 1)
energy_mma_kernel(const __nv_bfloat16* __restrict__ QH,
                  const __nv_bfloat16* __restrict__ QL,
                  const __nv_bfloat16* __restrict__ KH,
                  const __nv_bfloat16* __restrict__ KL,
                  float* __restrict__ E)
{
    __shared__ __align__(16) char sm[4 * EPLANE];
    uint32_t sb = smem_u32(sm);
    int tid = threadIdx.x;
    int wid = tid >> 5, lid = tid & 31;
    int g = lid >> 2, t = lid & 3;
    int wm = wid & 1, wn = wid >> 1;

    int b  = blockIdx.z;
    int m0 = blockIdx.y * 128;
    int n0 = blockIdx.x * 128;

    int row  = tid >> 1;
    int half = tid & 1;
    const __nv_bfloat16* srcs[4] = {
        QH + ((size_t)b * NDIM + m0 + row) * CQKD + half * 16,
        QL + ((size_t)b * NDIM + m0 + row) * CQKD + half * 16,
        KH + ((size_t)b * NDIM + n0 + row) * CQKD + half * 16,
        KL + ((size_t)b * NDIM + n0 + row) * CQKD + half * 16 };
#pragma unroll
    for (int p = 0; p < 4; p++) {
        uint32_t dst = sb + p * EPLANE + (uint32_t)row * (EP * 2) + half * 32;
        cp16(dst, srcs[p]);
        cp16(dst + 16, srcs[p] + 8);
    }
    CP_COMMIT(); CP_WAIT0();
    __syncthreads();

    float acc[4][4][4];
#pragma unroll
    for (int mt = 0; mt < 4; mt++)
#pragma unroll
        for (int nt = 0; nt < 4; nt++)
#pragma unroll
            for (int q = 0; q < 4; q++) acc[mt][nt][q] = 0.f;

#pragma unroll
    for (int ks = 0; ks < 2; ks++) {
        // A fragments via ldmatrix (hi and lo planes)
        uint32_t ah[4][4], al[4][4];
#pragma unroll
        for (int mt = 0; mt < 4; mt++) {
            uint32_t rowoff = (uint32_t)(wm * 64 + mt * 16 + (lid & 15)) * 80
                            + ks * 32 + (lid >> 4) * 16;
            ldm_x4(ah[mt], sb + rowoff);
            ldm_x4(al[mt], sb + EPLANE + rowoff);
        }
        // B fragments: each ldmatrix.x4 serves two n-tiles
        uint32_t bh[2][4], bl[2][4];
#pragma unroll
        for (int p = 0; p < 2; p++) {
            uint32_t rowoff = (uint32_t)(wn * 32 + p * 16 + (lid & 7) + ((lid >> 4) * 8)) * 80
                            + ((lid >> 3) & 1) * 16 + ks * 32;
            ldm_x4(bh[p], sb + 2 * EPLANE + rowoff);
            ldm_x4(bl[p], sb + 3 * EPLANE + rowoff);
        }
#pragma unroll
        for (int mt = 0; mt < 4; mt++)
#pragma unroll
            for (int nt = 0; nt < 4; nt++) {
                const uint32_t* bhp = &bh[nt >> 1][(nt & 1) * 2];
                const uint32_t* blp = &bl[nt >> 1][(nt & 1) * 2];
                mma_bf16(acc[mt][nt], ah[mt], bhp);
                mma_bf16(acc[mt][nt], ah[mt], blp);
                mma_bf16(acc[mt][nt], al[mt], bhp);
            }
    }

#pragma unroll
    for (int mt = 0; mt < 4; mt++) {
        int r0 = m0 + wm * 64 + mt * 16 + g;
#pragma unroll
        for (int nt = 0; nt < 4; nt++) {
            int col = n0 + wn * 32 + nt * 8 + 2 * t;
            size_t off0 = ((size_t)b * NDIM + r0) * NDIM + col;
            size_t off1 = ((size_t)b * NDIM + r0 + 8) * NDIM + col;
            float2 e0 = {acc[mt][nt][0] * ATT_SCALE, acc[mt][nt][1] * ATT_SCALE};
            float2 e1 = {acc[mt][nt][2] * ATT_SCALE, acc[mt][nt][3] * ATT_SCALE};
            *(float2*)(E + off0) = e0;
            *(float2*)(E + off1) = e1;
        }
    }
}

// ---------------- softmax: in-place fp32 + fp16 plane -------------------------
__global__ void softmax_kernel(float* __restrict__ A,
                               __half* __restrict__ AH)
{
    __shared__ float smax[8];
    __shared__ float ssum[8];
    size_t base = (size_t)blockIdx.x * NDIM;
    int tid = threadIdx.x;

    float4 v[4];
    float mx = -3.4e38f;
#pragma unroll
    for (int g = 0; g < 4; g++) {
        v[g] = *(const float4*)(A + base + (size_t)(g * 256 + tid) * 4);
        mx = fmaxf(mx, fmaxf(fmaxf(v[g].x, v[g].y), fmaxf(v[g].z, v[g].w)));
    }
#pragma unroll
    for (int o = 16; o > 0; o >>= 1) mx = fmaxf(mx, __shfl_xor_sync(0xffffffffu, mx, o));
    if ((tid & 31) == 0) smax[tid >> 5] = mx;
    __syncthreads();
    mx = smax[0];
#pragma unroll
    for (int w = 1; w < 8; w++) mx = fmaxf(mx, smax[w]);

    float s = 0.f;
#pragma unroll
    for (int g = 0; g < 4; g++) {
        v[g].x = __expf(v[g].x - mx); v[g].y = __expf(v[g].y - mx);
        v[g].z = __expf(v[g].z - mx); v[g].w = __expf(v[g].w - mx);
        s += v[g].x + v[g].y + v[g].z + v[g].w;
    }
#pragma unroll
    for (int o = 16; o > 0; o >>= 1) s += __shfl_xor_sync(0xffffffffu, s, o);
    if ((tid & 31) == 0) ssum[tid >> 5] = s;
    __syncthreads();
    s = 0.f;
#pragma unroll
    for (int w = 0; w < 8; w++) s += ssum[w];

    float inv = 1.0f / s;
#pragma unroll
    for (int g = 0; g < 4; g++) {
        v[g].x *= inv; v[g].y *= inv; v[g].z *= inv; v[g].w *= inv;
        size_t eoff = base + (size_t)(g * 256 + tid) * 4;
        *(float4*)(A + eoff) = v[g];
        __half2 h0 = __floats2half2_rn(v[g].x, v[g].y);
        __half2 h1 = __floats2half2_rn(v[g].z, v[g].w);
        uint32_t* ph = (uint32_t*)(AH + eoff);
        ph[0] = *(uint32_t*)&h0;
        ph[1] = *(uint32_t*)&h1;
    }
}

// ============== texture GEMM via single fp16 mma + ldmatrix ====================
// tex[b,c,m] = sum_n V[b,c,n] * attn[b,m,n];  out = tex + sketches
#define XSTAGE_BYTES (2 * EPLANE)       // V plane + A plane -> 20480
#define XSTAGES 4
#define XSMEM_BYTES (XSTAGES * XSTAGE_BYTES)   // 81920
#define XNCH (NDIM / 32)                // 128

__device__ __forceinline__ void x_load_chunk(int j, uint32_t sb_base, int tid,
                                             const __half* VHb, const __half* AHb)
{
    uint32_t sb = sb_base + (uint32_t)(j & (XSTAGES - 1)) * XSTAGE_BYTES;
    int row  = tid >> 1;
    int half = tid & 1;
    int kt = j * 32;

    const __half* s0 = VHb + (size_t)row * NDIM + kt + half * 16;
    const __half* s1 = AHb + (size_t)row * NDIM + kt + half * 16;
    uint32_t d0 = sb + (uint32_t)row * 80 + half * 32;
    uint32_t d1 = d0 + EPLANE;
    cp16(d0, s0); cp16(d0 + 16, s0 + 8);
    cp16(d1, s1); cp16(d1 + 16, s1 + 8);
}

__global__ void __launch_bounds__(256, 2)
texture_mma_kernel(const __half* __restrict__ VH,
                   const __half* __restrict__ AH,
                   const float* __restrict__ SK,
                   float* __restrict__ TEX,
                   float* __restrict__ OUT)
{
    extern __shared__ char smem[];
    uint32_t sb_base = smem_u32(smem);
    int tid = threadIdx.x;
    int wid = tid >> 5, lid = tid & 31;
    int g = lid >> 2, t = lid & 3;
    int wm = wid & 1, wn = wid >> 1;

    int b  = blockIdx.z;
    int i0 = blockIdx.y * 128;
    int j0 = blockIdx.x * 128;

    const __half* VHb = VH + ((size_t)b * CDIM + i0) * NDIM;
    const __half* AHb = AH + ((size_t)b * NDIM + j0) * NDIM;

    float acc[4][4][4];
#pragma unroll
    for (int mt = 0; mt < 4; mt++)
#pragma unroll
        for (int nt = 0; nt < 4; nt++)
#pragma unroll
            for (int q = 0; q < 4; q++) acc[mt][nt][q] = 0.f;

    x_load_chunk(0, sb_base, tid, VHb, AHb); CP_COMMIT();
    x_load_chunk(1, sb_base, tid, VHb, AHb); CP_COMMIT();
    x_load_chunk(2, sb_base, tid, VHb, AHb); CP_COMMIT();

    // precomputed ldmatrix lane offsets
    uint32_t a_lane = (uint32_t)(lid & 15) * 80 + (uint32_t)(lid >> 4) * 16;
    uint32_t b_lane = (uint32_t)((lid & 7) + ((lid >> 4) * 8)) * 80
                    + (uint32_t)((lid >> 3) & 1) * 16;

    for (int i = 0; i < XNCH; i++) {
        CP_WAIT2();
        __syncthreads();
        if (i + 3 < XNCH) x_load_chunk(i + 3, sb_base, tid, VHb, AHb);
        CP_COMMIT();

        uint32_t sA = sb_base + (uint32_t)(i & (XSTAGES - 1)) * XSTAGE_BYTES;
        uint32_t sB = sA + EPLANE;

#pragma unroll
        for (int ks = 0; ks < 2; ks++) {
            uint32_t af[4][4];
#pragma unroll
            for (int mt = 0; mt < 4; mt++)
                ldm_x4(af[mt], sA + (uint32_t)(wm * 64 + mt * 16) * 80 + ks * 32 + a_lane);
            uint32_t bq[2][4];
#pragma unroll
            for (int p = 0; p < 2; p++)
                ldm_x4(bq[p], sB + (uint32_t)(wn * 32 + p * 16) * 80 + ks * 32 + b_lane);
#pragma unroll
            for (int mt = 0; mt < 4; mt++)
#pragma unroll
                for (int nt = 0; nt < 4; nt++)
                    mma_f16(acc[mt][nt], af[mt], &bq[nt >> 1][(nt & 1) * 2]);
        }
        __syncthreads();
    }
    CP_WAIT0();

#pragma unroll
    for (int mt = 0; mt < 4; mt++) {
        int r0 = i0 + wm * 64 + mt * 16 + g;
#pragma unroll
        for (int nt = 0; nt < 4; nt++) {
            int col = j0 + wn * 32 + nt * 8 + 2 * t;
            size_t off0 = ((size_t)b * CDIM + r0) * NDIM + col;
            size_t off1 = ((size_t)b * CDIM + r0 + 8) * NDIM + col;
            float2 t0 = {acc[mt][nt][0], acc[mt][nt][1]};
            float2 t1 = {acc[mt][nt][2], acc[mt][nt][3]};
            float2 s0 = *(const float2*)(SK + off0);
            float2 s1 = *(const float2*)(SK + off1);
            *(float2*)(TEX + off0) = t0;
            *(float2*)(TEX + off1) = t1;
            float2 o0 = {t0.x + s0.x, t0.y + s0.y};
            float2 o1 = {t1.x + s1.x, t1.y + s1.y};
            *(float2*)(OUT + off0) = o0;
            *(float2*)(OUT + off1) = o1;
        }
    }
}

// ---------------- launch -------------------------------------------------------
extern "C" void kernel_launch(void* const* d_in, const int* in_sizes, int n_in,
                              void* d_out, int out_size)
{
    const float* sk = (const float*)d_in[0];
    const float* ex = (const float*)d_in[1];
    const float* Wq = (const float*)d_in[2];
    const float* bq = (const float*)d_in[3];
    const float* Wk = (const float*)d_in[4];
    const float* bk = (const float*)d_in[5];
    const float* Wv = (const float*)d_in[6];
    const float* bv = (const float*)d_in[7];

    const size_t BCN = (size_t)BATCH * CDIM * NDIM;
    const size_t BNN = (size_t)BATCH * NDIM * NDIM;

    float* out_p = (float*)d_out;
    float* tex_p;
    float* attn_p;

    if ((size_t)(unsigned)out_size >= 2 * BCN + BNN) {
        tex_p  = out_p + BCN;
        attn_p = out_p + 2 * BCN;
    } else {
        void* p;
        cudaGetSymbolAddress(&p, g_tex_fb);  tex_p  = (float*)p;
        cudaGetSymbolAddress(&p, g_attn_fb); attn_p = (float*)p;
    }

    __nv_bfloat16 *qh, *ql, *kh, *kl;
    __half *vh, *ah;
    { void* p;
      cudaGetSymbolAddress(&p, g_qh); qh = (__nv_bfloat16*)p;
      cudaGetSymbolAddress(&p, g_ql); ql = (__nv_bfloat16*)p;
      cudaGetSymbolAddress(&p, g_kh); kh = (__nv_bfloat16*)p;
      cudaGetSymbolAddress(&p, g_kl); kl = (__nv_bfloat16*)p;
      cudaGetSymbolAddress(&p, g_vh); vh = (__half*)p;
      cudaGetSymbolAddress(&p, g_ah); ah = (__half*)p; }

    // 1) q, k projections -> bf16 hi/lo
    dim3 gproj(NDIM / 256, BATCH);
    proj_small_kernel<<<gproj, 256>>>(sk, Wq, bq, qh, ql);
    proj_small_kernel<<<gproj, 256>>>(ex, Wk, bk, kh, kl);

    // 2) v projection -> fp16
    dim3 gv(NDIM / 256, CDIM / 32, BATCH);
    proj_v_kernel<<<gv, 256>>>(ex, Wv, bv, vh);

    // 3) energy via mma -> raw scores into attention buffer
    dim3 ge(NDIM / 128, NDIM / 128, BATCH);
    energy_mma_kernel<<<ge, 256>>>(qh, ql, kh, kl, attn_p);

    // 4) softmax in place + fp16 plane
    softmax_kernel<<<BATCH * NDIM, 256>>>(attn_p, ah);

    // 5) texture GEMM via fp16 mma + ldmatrix + residual epilogue
    static int smem_set = 0;
    if (!smem_set) {
        cudaFuncSetAttribute(texture_mma_kernel,
                             cudaFuncAttributeMaxDynamicSharedMemorySize, XSMEM_BYTES);
        smem_set = 1;
    }
    dim3 gt(NDIM / 128, CDIM / 128, BATCH);
    texture_mma_kernel<<<gt, 256, XSMEM_BYTES>>>(vh, ah, sk, tex_p, out_p);
}